// round 14
// baseline (speedup 1.0000x reference)
#include <cuda_runtime.h>
#include <cuda_fp16.h>
#include <math.h>
#include <stdint.h>

// Problem constants
#define NFEAT 16384          // B*H*W = 16*32*32
#define KCODE 8192           // codebook size
#define CDIM  256            // codebook dim
#define BATCH 16
#define HDIM  32
#define WDIM  32

// Output layout (float32, concatenated in reference tuple order)
#define OUT_ZQ    0
#define OUT_LOSS  4194304
#define OUT_QERR  4194305
#define OUT_UTIL  4194306
#define OUT_PERP  4194307
#define OUT_NEMB  4194308
#define OUT_NPROB 6291460

// GEMM tiling (fp16 m16n8k16; BM64 x BN256, 256 thr, 2 CTAs/SM)
#define BM 64
#define BN 256
#define NJB (KCODE / BN)     // 32 j-blocks
#define BK 64                // fp16 k-chunk per stage
#define NKB (CDIM / BK)      // 4
#define ROWB 160             // 80 halves per row (padded) -> conflict-free LDS.64

// codebook pre-scale 2^14 (exact); epilogue rescale -2*2^-14 = -2^-13
#define ESCALE 16384.0f
#define DSCALE (-1.0f / 8192.0f)

// candidate window: > 2*ulp(256) + 2*fp16_approx_err
#define EPSB 1.2e-4f
#define MAXX (1 << 21)

// Scratch (device globals; no dynamic allocation allowed)
__device__ float              g_zf[NFEAT * CDIM];
__device__ __half             g_zh[NFEAT * CDIM];
__device__ __half             g_eh[KCODE * CDIM];   // embedding * 2^14, fp16
__device__ float              g_S[NFEAT];
__device__ float              g_e2[KCODE];
__device__ unsigned long long g_blockmin[NFEAT][NJB];
__device__ unsigned long long g_exkey[NFEAT];
__device__ unsigned int       g_extras[MAXX];
__device__ unsigned int       g_xcnt;
__device__ unsigned long long g_maxkey[KCODE];
__device__ unsigned int       g_hist[KCODE];
__device__ int                g_token[NFEAT];
__device__ float              g_sse;
__device__ float              g_ent;
__device__ unsigned int       g_util;
__device__ unsigned int       g_done;

__device__ __forceinline__ unsigned int ford(float f) {
    unsigned int u = __float_as_uint(f);
    return u ^ ((((int)u) >> 31) | 0x80000000u);
}
__device__ __forceinline__ float unford(unsigned int u) {
    unsigned int v = (u & 0x80000000u) ? (u ^ 0x80000000u) : ~u;
    return __uint_as_float(v);
}

// exact distance on the reference fp32 grid, via compensated fp32 dot.
__device__ __forceinline__ float exact_d32(const float* __restrict__ emb,
                                           int n, int j, int lane) {
    const float* zr = g_zf + (size_t)n * CDIM;
    const float* er = emb + (size_t)j * CDIM;
    float hi = 0.0f, lo = 0.0f;
#pragma unroll
    for (int c = 0; c < CDIM / 32; c++) {
        float a = zr[lane + 32 * c], b = er[lane + 32 * c];
        float p = __fmul_rn(a, b);
        float perr = fmaf(a, b, -p);
        float s = __fadd_rn(hi, p);
        float bp = __fsub_rn(s, hi);
        float e = __fadd_rn(__fsub_rn(hi, __fsub_rn(s, bp)), __fsub_rn(p, bp));
        hi = s;
        lo = __fadd_rn(lo, __fadd_rn(e, perr));
    }
#pragma unroll
    for (int m = 16; m; m >>= 1) {
        float oh = __shfl_xor_sync(0xffffffffu, hi, m);
        float ol = __shfl_xor_sync(0xffffffffu, lo, m);
        float s = __fadd_rn(hi, oh);
        float bp = __fsub_rn(s, hi);
        float e = __fadd_rn(__fsub_rn(hi, __fsub_rn(s, bp)), __fsub_rn(oh, bp));
        hi = s;
        lo = __fadd_rn(__fadd_rn(lo, ol), e);
    }
    float dotf = __fadd_rn(hi, lo);
    return __fsub_rn(__fadd_rn(g_S[n], g_e2[j]), 2.0f * dotf);
}

// ---------------------------------------------------------------------------
// K1: fused init + transpose/prep + e2 (independent block ranges)
// blocks [0,64): init; [64,576): prep; [576,1600): e2
// ---------------------------------------------------------------------------
__global__ void __launch_bounds__(256) front_kernel(const float* __restrict__ z,
                                                    const float* __restrict__ emb) {
    __shared__ float tile[32][CDIM + 1];
    int bid = blockIdx.x;
    int tid = threadIdx.x;
    if (bid < 64) {
        int i = bid * 256 + tid;
        if (i < NFEAT) g_exkey[i] = ~0ull;
        if (i < KCODE) { g_maxkey[i] = ~0ull; g_hist[i] = 0u; }
        if (i == 0) {
            g_sse = 0.0f; g_ent = 0.0f; g_util = 0u; g_xcnt = 0u; g_done = 0u;
        }
        return;
    }
    int tx = tid & 31, ty = tid >> 5;
    if (bid < 576) {
        int blk = bid - 64;
        int b = blk >> 5, h = blk & 31;
        const float* zp = z + (size_t)b * (CDIM * HDIM * WDIM) + h * WDIM;
#pragma unroll
        for (int i = 0; i < 32; i++) {
            int c = i * 8 + ty;
            tile[tx][c] = zp[c * (HDIM * WDIM) + tx];
        }
        __syncthreads();
        int nbase = b * 1024 + h * 32;
#pragma unroll
        for (int j = 0; j < 4; j++) {
            int w = ty * 4 + j;
            int n = nbase + w;
            float s = 0.0f;
#pragma unroll
            for (int i = 0; i < 8; i++) {
                int c = tx + 32 * i;
                float v = tile[w][c];
                g_zf[(size_t)n * CDIM + c] = v;
                g_zh[(size_t)n * CDIM + c] = __float2half_rn(v);
                s += v * v;
            }
#pragma unroll
            for (int m = 16; m; m >>= 1) s += __shfl_xor_sync(0xffffffffu, s, m);
            if (tx == 0) g_S[n] = s;
        }
        return;
    }
    {
        int j = (bid - 576) * 8 + ty;
        float s = 0.0f;
#pragma unroll
        for (int i = 0; i < 8; i++) {
            float v = emb[(size_t)j * CDIM + tx + 32 * i];
            g_eh[(size_t)j * CDIM + tx + 32 * i] = __float2half_rn(v * ESCALE);
            s += v * v;
        }
#pragma unroll
        for (int m = 16; m; m >>= 1) s += __shfl_xor_sync(0xffffffffu, s, m);
        if (tx == 0) g_e2[j] = s;
    }
}

// ---------------------------------------------------------------------------
// K3: fp16 m16n8k16 GEMM, 256 threads (8 warps 1Mx8N), 2 CTAs/SM.
// Single barrier per k-block; cross-ks B-fragment prefetch.
// ---------------------------------------------------------------------------
#define SM_ROWKEY 0             // 64 u64  [0,512)
#define SM_COLKEY 512           // 256 u64 [512,2560)
#define SM_SS     2560          // 64 f    [2560,2816)
#define SM_E2S    2816          // 256 f   [2816,3840)
#define SM_DATA   3840
#define STAGE_A   (BM * ROWB)               // 10240
#define STAGE_B   (BN * ROWB)               // 40960
#define STAGE_SZ  (STAGE_A + STAGE_B)       // 51200
#define GEMM_SMEM (SM_DATA + 2 * STAGE_SZ)  // 106240

__device__ __forceinline__ void cpa16(uint32_t dst, const void* src) {
    asm volatile("cp.async.cg.shared.global [%0], [%1], 16;"
                 :: "r"(dst), "l"(src));
}

#define MMA16(d, a0, a1, a2, a3, b0, b1)                                     \
    asm volatile(                                                            \
        "mma.sync.aligned.m16n8k16.row.col.f32.f16.f16.f32 "                 \
        "{%0,%1,%2,%3},{%4,%5,%6,%7},{%8,%9},{%0,%1,%2,%3};"                 \
        : "+f"(d[0]), "+f"(d[1]), "+f"(d[2]), "+f"(d[3])                     \
        : "r"(a0), "r"(a1), "r"(a2), "r"(a3), "r"(b0), "r"(b1))

extern __shared__ char dynsmem[];

__global__ void __launch_bounds__(256, 2)
gemm_mma_kernel(const float* __restrict__ emb) {
    const int tid  = threadIdx.x;
    const int lane = tid & 31;
    const int wn   = tid >> 5;      // warp 0..7 = N split
    const int gid  = lane >> 2;     // 0..7
    const int tig  = lane & 3;      // 0..3
    const int m0   = blockIdx.y * BM;
    const int j0   = blockIdx.x * BN;

    unsigned long long* rowkey = (unsigned long long*)(dynsmem + SM_ROWKEY);
    unsigned long long* colkey = (unsigned long long*)(dynsmem + SM_COLKEY);
    float* Ss  = (float*)(dynsmem + SM_SS);
    float* e2s = (float*)(dynsmem + SM_E2S);

    uint32_t smbase;
    asm("{ .reg .u64 t; cvta.to.shared.u64 t, %1; cvt.u32.u64 %0, t; }"
        : "=r"(smbase) : "l"(dynsmem));

    const int t8 = tid >> 3;            // 0..31
    const int c8 = tid & 7;             // 0..7
    const __half* gA0 = g_zh + (size_t)(m0 + t8) * CDIM + c8 * 8;
    const __half* gB0 = g_eh + (size_t)(j0 + t8) * CDIM + c8 * 8;
    const uint32_t dA0 = smbase + SM_DATA + t8 * ROWB + c8 * 16;
    const uint32_t dB0 = smbase + SM_DATA + STAGE_A + t8 * ROWB + c8 * 16;

    auto load_kb = [&](int s, int kb) {
        uint32_t so = s * STAGE_SZ;
        const __half* ga = gA0 + kb * BK;
        const __half* gb = gB0 + kb * BK;
#pragma unroll
        for (int i = 0; i < 2; i++)
            cpa16(dA0 + so + i * 32 * ROWB, ga + (size_t)i * 32 * CDIM);
#pragma unroll
        for (int i = 0; i < 8; i++)
            cpa16(dB0 + so + i * 32 * ROWB, gb + (size_t)i * 32 * CDIM);
    };

    if (tid < 64) { rowkey[tid] = ~0ull; Ss[tid] = g_S[m0 + tid]; }
    colkey[tid] = ~0ull;
    e2s[tid] = g_e2[j0 + tid];

    load_kb(0, 0);
    asm volatile("cp.async.commit_group;" ::: "memory");

    float acc[4][4][4];
#pragma unroll
    for (int nt = 0; nt < 4; nt++)
#pragma unroll
        for (int mt = 0; mt < 4; mt++)
#pragma unroll
            for (int c = 0; c < 4; c++) acc[nt][mt][c] = 0.0f;

    const int aBase2 = gid * (ROWB / 8) + tig;
    const int bBase2 = (wn * 32 + gid) * (ROWB / 8) + tig;

#pragma unroll 1
    for (int kb = 0; kb < NKB; kb++) {
        asm volatile("cp.async.wait_group 0;" ::: "memory");
        __syncthreads();   // single barrier per k-block

        const uint2* Af2 =
            (const uint2*)(dynsmem + SM_DATA + (kb & 1) * STAGE_SZ);
        const uint2* Bf2 = Af2 + STAGE_A / 8;

        // prefetch B fragments for ks=0
        uint2 bv[4];
#pragma unroll
        for (int nt = 0; nt < 4; nt++)
            bv[nt] = Bf2[bBase2 + nt * 8 * (ROWB / 8)];

#pragma unroll
        for (int ks = 0; ks < BK / 16; ks++) {        // 4 k16-steps
            const int ko = ks * 4;
            uint2 alo[4], ahi[4];
#pragma unroll
            for (int mt = 0; mt < 4; mt++) {
                int o = aBase2 + mt * 16 * (ROWB / 8) + ko;
                alo[mt] = Af2[o];
                ahi[mt] = Af2[o + 8 * (ROWB / 8)];
            }
            // prefetch B fragments for ks+1 under this step's MMAs
            uint2 bn[4];
            if (ks + 1 < BK / 16) {
#pragma unroll
                for (int nt = 0; nt < 4; nt++)
                    bn[nt] = Bf2[bBase2 + nt * 8 * (ROWB / 8) + ko + 4];
            }
#pragma unroll
            for (int nt = 0; nt < 4; nt++)
#pragma unroll
                for (int mt = 0; mt < 4; mt++)
                    MMA16(acc[nt][mt], alo[mt].x, ahi[mt].x,
                          alo[mt].y, ahi[mt].y, bv[nt].x, bv[nt].y);
            if (ks == 0 && kb + 1 < NKB) {
                load_kb((kb + 1) & 1, kb + 1);
                asm volatile("cp.async.commit_group;" ::: "memory");
            }
            if (ks + 1 < BK / 16) {
#pragma unroll
                for (int nt = 0; nt < 4; nt++) bv[nt] = bn[nt];
            }
        }
    }

    // ---- epilogue pass 1: d -> acc (in place), argmin/argmax ----
    float S_lo[4], S_hi[4];
#pragma unroll
    for (int mt = 0; mt < 4; mt++) {
        S_lo[mt] = Ss[mt * 16 + gid];
        S_hi[mt] = Ss[mt * 16 + gid + 8];
    }
    float bd_lo[4], bd_hi[4];
    int   bj_lo[4], bj_hi[4];
#pragma unroll
    for (int mt = 0; mt < 4; mt++) {
        bd_lo[mt] = __int_as_float(0x7f800000); bj_lo[mt] = 0;
        bd_hi[mt] = __int_as_float(0x7f800000); bj_hi[mt] = 0;
    }

#pragma unroll
    for (int nt = 0; nt < 4; nt++) {
        const int ca = wn * 32 + nt * 8 + 2 * tig;
        const float e2a = e2s[ca], e2b = e2s[ca + 1];
        const int ja = j0 + ca;
        float cva = __int_as_float(0xff800000), cvb = cva;   // -inf
        int cia = 0, cib = 0;
#pragma unroll
        for (int mt = 0; mt < 4; mt++) {
            const int rlo = m0 + mt * 16 + gid;
            float d00 = fmaf(acc[nt][mt][0], DSCALE, S_lo[mt] + e2a);
            float d01 = fmaf(acc[nt][mt][1], DSCALE, S_lo[mt] + e2b);
            float d10 = fmaf(acc[nt][mt][2], DSCALE, S_hi[mt] + e2a);
            float d11 = fmaf(acc[nt][mt][3], DSCALE, S_hi[mt] + e2b);
            acc[nt][mt][0] = d00; acc[nt][mt][1] = d01;
            acc[nt][mt][2] = d10; acc[nt][mt][3] = d11;
            if (d00 < bd_lo[mt]) { bd_lo[mt] = d00; bj_lo[mt] = ja; }
            if (d01 < bd_lo[mt]) { bd_lo[mt] = d01; bj_lo[mt] = ja + 1; }
            if (d10 < bd_hi[mt]) { bd_hi[mt] = d10; bj_hi[mt] = ja; }
            if (d11 < bd_hi[mt]) { bd_hi[mt] = d11; bj_hi[mt] = ja + 1; }
            if (d00 > cva) { cva = d00; cia = rlo; }
            if (d10 > cva) { cva = d10; cia = rlo + 8; }
            if (d01 > cvb) { cvb = d01; cib = rlo; }
            if (d11 > cvb) { cvb = d11; cib = rlo + 8; }
        }
#pragma unroll
        for (int off = 4; off < 32; off <<= 1) {
            float ov = __shfl_xor_sync(0xffffffffu, cva, off);
            int   oi = __shfl_xor_sync(0xffffffffu, cia, off);
            if (ov > cva || (ov == cva && oi < cia)) { cva = ov; cia = oi; }
            ov = __shfl_xor_sync(0xffffffffu, cvb, off);
            oi = __shfl_xor_sync(0xffffffffu, cib, off);
            if (ov > cvb || (ov == cvb && oi < cib)) { cvb = ov; cib = oi; }
        }
        if (gid == 0) {
            atomicMin(&colkey[ca],
                      (((unsigned long long)(~ford(cva))) << 32) | (unsigned)cia);
            atomicMin(&colkey[ca + 1],
                      (((unsigned long long)(~ford(cvb))) << 32) | (unsigned)cib);
        }
    }
#pragma unroll
    for (int mt = 0; mt < 4; mt++) {
        unsigned long long klo =
            (((unsigned long long)ford(bd_lo[mt])) << 32) | (unsigned)bj_lo[mt];
        unsigned long long khi =
            (((unsigned long long)ford(bd_hi[mt])) << 32) | (unsigned)bj_hi[mt];
#pragma unroll
        for (int off = 1; off < 4; off <<= 1) {
            klo = min(klo, __shfl_xor_sync(0xffffffffu, klo, off));
            khi = min(khi, __shfl_xor_sync(0xffffffffu, khi, off));
        }
        if (tig == 0) {
            atomicMin(&rowkey[mt * 16 + gid], klo);
            atomicMin(&rowkey[mt * 16 + gid + 8], khi);
        }
    }
    __syncthreads();

    if (tid < 64) g_blockmin[m0 + tid][blockIdx.x] = rowkey[tid];
    atomicMin(&g_maxkey[j0 + tid], colkey[tid]);

    // ---- epilogue pass 2: append near-tie candidates (d cached in acc) ----
#pragma unroll
    for (int mt = 0; mt < 4; mt++) {
        const int rl = mt * 16 + gid;
        const int rh = rl + 8;
        const unsigned long long rkl = rowkey[rl];
        const unsigned long long rkh = rowkey[rh];
        const float vl = unford((unsigned)(rkl >> 32)) + EPSB;
        const float vh = unford((unsigned)(rkh >> 32)) + EPSB;
#pragma unroll
        for (int nt = 0; nt < 4; nt++) {
            const int ca = wn * 32 + nt * 8 + 2 * tig;
            const unsigned ja = (unsigned)(j0 + ca);
            float d00 = acc[nt][mt][0];
            float d01 = acc[nt][mt][1];
            float d10 = acc[nt][mt][2];
            float d11 = acc[nt][mt][3];
            if (d00 < vl) {
                unsigned long long k = (((unsigned long long)ford(d00)) << 32) | ja;
                if (k != rkl) {
                    unsigned slot = atomicAdd(&g_xcnt, 1u);
                    if (slot < MAXX)
                        g_extras[slot] = ((unsigned)(m0 + rl) << 13) | ja;
                }
            }
            if (d01 < vl) {
                unsigned long long k = (((unsigned long long)ford(d01)) << 32) | (ja + 1);
                if (k != rkl) {
                    unsigned slot = atomicAdd(&g_xcnt, 1u);
                    if (slot < MAXX)
                        g_extras[slot] = ((unsigned)(m0 + rl) << 13) | (ja + 1);
                }
            }
            if (d10 < vh) {
                unsigned long long k = (((unsigned long long)ford(d10)) << 32) | ja;
                if (k != rkh) {
                    unsigned slot = atomicAdd(&g_xcnt, 1u);
                    if (slot < MAXX)
                        g_extras[slot] = ((unsigned)(m0 + rh) << 13) | ja;
                }
            }
            if (d11 < vh) {
                unsigned long long k = (((unsigned long long)ford(d11)) << 32) | (ja + 1);
                if (k != rkh) {
                    unsigned slot = atomicAdd(&g_xcnt, 1u);
                    if (slot < MAXX)
                        g_extras[slot] = ((unsigned)(m0 + rh) << 13) | (ja + 1);
                }
            }
        }
    }
}

// ---------------------------------------------------------------------------
// K4a: exact recompute of appended extras
// ---------------------------------------------------------------------------
__global__ void __launch_bounds__(256) extras_kernel(const float* __restrict__ emb) {
    const unsigned cnt = min(g_xcnt, (unsigned)MAXX);
    const int lane = threadIdx.x & 31;
    const int wid = (blockIdx.x * blockDim.x + threadIdx.x) >> 5;
    const int nw = (gridDim.x * blockDim.x) >> 5;
    for (unsigned i = wid; i < cnt; i += nw) {
        unsigned e = g_extras[i];
        int n = e >> 13;
        int j = e & 8191;
        float d32 = exact_d32(emb, n, j, lane);
        unsigned long long key =
            (((unsigned long long)ford(d32)) << 32) | (unsigned)j;
        if (lane == 0) atomicMin(&g_exkey[n], key);
    }
}

// ---------------------------------------------------------------------------
// K4b: per-row token resolution (+ histogram); NJB==32 -> 1 key per lane
// ---------------------------------------------------------------------------
__global__ void __launch_bounds__(256) tokenfix_kernel(const float* __restrict__ emb) {
    const int lane = threadIdx.x & 31;
    const int wid = (blockIdx.x * blockDim.x + threadIdx.x) >> 5;
    const int nw = (gridDim.x * blockDim.x) >> 5;
    for (int n = wid; n < NFEAT; n += nw) {
        unsigned long long k = g_blockmin[n][lane];   // NJB == 32
        unsigned long long gm = k;
#pragma unroll
        for (int m = 16; m; m >>= 1)
            gm = min(gm, __shfl_xor_sync(0xffffffffu, gm, m));
        float thresh = unford((unsigned)(gm >> 32)) + EPSB;
        bool cand = unford((unsigned)(k >> 32)) < thresh;
        unsigned bal = __ballot_sync(0xffffffffu, cand);
        unsigned long long ex = g_exkey[n];
        unsigned tok;
        if (__popc(bal) == 1 && ex == ~0ull) {
            tok = (unsigned)(gm & 0xffffffffull);
        } else {
            unsigned long long best = ex;
            unsigned b = bal;
            while (b) {
                int src = __ffs(b) - 1;
                b &= b - 1;
                unsigned jj = __shfl_sync(0xffffffffu,
                                          (unsigned)(k & 0xffffffffull), src);
                float d32 = exact_d32(emb, n, (int)jj, lane);
                unsigned long long key =
                    (((unsigned long long)ford(d32)) << 32) | jj;
                best = min(best, key);
            }
            tok = (unsigned)(best & 0xffffffffull);
        }
        if (lane == 0) {
            g_token[n] = (int)tok;
            atomicAdd(&g_hist[tok], 1u);
        }
    }
}

// ---------------------------------------------------------------------------
// K5: fused z_q output + SSE (blocks [0,512)), per-code update (rest),
// and finalize scalars in the last block to finish.
// ---------------------------------------------------------------------------
__global__ void __launch_bounds__(256) back_kernel(const float* __restrict__ emb,
                                                   const float* __restrict__ eprob,
                                                   float* __restrict__ out) {
    __shared__ float rowbuf[32][CDIM + 1];
    __shared__ int stok[32];
    __shared__ float red[8];
    int bid = blockIdx.x;
    int tid = threadIdx.x;
    if (bid < 512) {
        int b = bid >> 5, h = bid & 31;
        int nbase = b * 1024 + h * 32;
        if (tid < 32) stok[tid] = g_token[nbase + tid];
        __syncthreads();
        float acc = 0.0f;
#pragma unroll 4
        for (int w = 0; w < 32; w++) {
            float v  = emb[(size_t)stok[w] * CDIM + tid];
            float zv = g_zf[(size_t)(nbase + w) * CDIM + tid];
            float diff = __fsub_rn(v, zv);
            acc = fmaf(diff, diff, acc);
            rowbuf[w][tid] = __fadd_rn(zv, diff);
        }
        float s = acc;
#pragma unroll
        for (int m = 16; m; m >>= 1) s += __shfl_xor_sync(0xffffffffu, s, m);
        if ((tid & 31) == 0) red[tid >> 5] = s;
        __syncthreads();
        if (tid == 0) {
            float t = 0.0f;
#pragma unroll
            for (int i = 0; i < 8; i++) t += red[i];
            atomicAdd(&g_sse, t);
        }
        int tx = tid & 31, ty = tid >> 5;
#pragma unroll
        for (int i = 0; i < 32; i++) {
            int c = i * 8 + ty;
            out[OUT_ZQ + (((size_t)b * CDIM + c) * HDIM + h) * WDIM + tx] =
                rowbuf[tx][c];
        }
    } else {
        int j = bid - 512;
        int c = tid;
        unsigned hcnt = g_hist[j];
        float avg = (float)hcnt * (1.0f / 16384.0f);
        float np  = __fadd_rn(__fmul_rn(eprob[j], 0.99f), __fmul_rn(avg, 0.01f));
        float t = __fmul_rn(np, 8192.0f);
        t = __fmul_rn(t, 10.0f);
        t = __fdiv_rn(t, 0.01f);
        float decay = expf(-t - 0.001f);
        float omd = __fsub_rn(1.0f, decay);
        if (c == 0) {
            out[OUT_NPROB + j] = np;
            atomicAdd(&g_ent, avg * logf(avg + 1e-10f));
            if (hcnt > 0) atomicAdd(&g_util, 1u);
        }
        int fi = (int)(g_maxkey[j] & 0xffffffffull);
        float rf = g_zf[(size_t)fi * CDIM + c];
        float e  = emb[(size_t)j * CDIM + c];
        out[OUT_NEMB + (size_t)j * CDIM + c] =
            __fadd_rn(__fmul_rn(e, omd), __fmul_rn(rf, decay));
    }
    // last block to finish computes final scalars (deterministic: final
    // atomic totals are order-independent)
    __syncthreads();
    __threadfence();
    if (tid == 0) {
        unsigned prev = atomicAdd(&g_done, 1u);
        if (prev == gridDim.x - 1) {
            float sse = g_sse;
            float mse = sse / 4194304.0f;
            out[OUT_LOSS] = __fadd_rn(__fmul_rn(0.25f, mse), mse);
            out[OUT_QERR] = sse / 16384.0f;
            out[OUT_UTIL] = (float)g_util / 8192.0f;
            out[OUT_PERP] = expf(-g_ent);
        }
    }
}

// ---------------------------------------------------------------------------
extern "C" void kernel_launch(void* const* d_in, const int* in_sizes, int n_in,
                              void* d_out, int out_size) {
    (void)in_sizes; (void)n_in; (void)out_size;
    const float* z     = (const float*)d_in[0];
    const float* emb   = (const float*)d_in[1];
    const float* eprob = (const float*)d_in[2];
    float* out = (float*)d_out;

    static int smem_set = 0;
    if (!smem_set) {
        cudaFuncSetAttribute(gemm_mma_kernel,
                             cudaFuncAttributeMaxDynamicSharedMemorySize,
                             GEMM_SMEM);
        smem_set = 1;
    }

    front_kernel<<<1600, 256>>>(z, emb);
    gemm_mma_kernel<<<dim3(NJB, NFEAT / BM), 256, GEMM_SMEM>>>(emb);
    extras_kernel<<<512, 256>>>(emb);
    tokenfix_kernel<<<1024, 256>>>(emb);
    back_kernel<<<512 + KCODE, 256>>>(emb, eprob, out);
}

// round 15
// speedup vs baseline: 1.0090x; 1.0090x over previous
#include <cuda_runtime.h>
#include <cuda_fp16.h>
#include <math.h>
#include <stdint.h>

// Problem constants
#define NFEAT 16384          // B*H*W = 16*32*32
#define KCODE 8192           // codebook size
#define CDIM  256            // codebook dim
#define BATCH 16
#define HDIM  32
#define WDIM  32

// Output layout (float32, concatenated in reference tuple order)
#define OUT_ZQ    0
#define OUT_LOSS  4194304
#define OUT_QERR  4194305
#define OUT_UTIL  4194306
#define OUT_PERP  4194307
#define OUT_NEMB  4194308
#define OUT_NPROB 6291460

// GEMM tiling (fp16 m16n8k16; BM64 x BN256, 256 thr, 2 CTAs/SM)
#define BM 64
#define BN 256
#define NJB (KCODE / BN)     // 32 j-blocks
#define BK 64                // fp16 k-chunk per stage
#define NKB (CDIM / BK)      // 4
#define ROWB 160             // 80 halves per row (padded) -> conflict-free LDS.64

// codebook pre-scale 2^14 (exact); epilogue rescale -2*2^-14 = -2^-13
#define ESCALE 16384.0f
#define DSCALE (-1.0f / 8192.0f)

// candidate window: > 2*ulp(256) + 2*fp16_approx_err
#define EPSB 1.2e-4f
#define MAXX (1 << 21)

// Scratch (device globals; no dynamic allocation allowed)
__device__ float              g_zf[NFEAT * CDIM];
__device__ __half             g_zh[NFEAT * CDIM];
__device__ __half             g_eh[KCODE * CDIM];   // embedding * 2^14, fp16
__device__ float              g_S[NFEAT];
__device__ float              g_e2[KCODE];
__device__ unsigned long long g_blockmin[NFEAT][NJB];
__device__ unsigned long long g_exkey[NFEAT];
__device__ unsigned int       g_extras[MAXX];
__device__ unsigned int       g_xcnt;
__device__ unsigned long long g_maxkey[KCODE];
__device__ unsigned int       g_hist[KCODE];
__device__ int                g_token[NFEAT];
__device__ float              g_sse;
__device__ float              g_ent;
__device__ unsigned int       g_util;

__device__ __forceinline__ unsigned int ford(float f) {
    unsigned int u = __float_as_uint(f);
    return u ^ ((((int)u) >> 31) | 0x80000000u);
}
__device__ __forceinline__ float unford(unsigned int u) {
    unsigned int v = (u & 0x80000000u) ? (u ^ 0x80000000u) : ~u;
    return __uint_as_float(v);
}

// exact distance on the reference fp32 grid, via compensated fp32 dot.
__device__ __forceinline__ float exact_d32(const float* __restrict__ emb,
                                           int n, int j, int lane) {
    const float* zr = g_zf + (size_t)n * CDIM;
    const float* er = emb + (size_t)j * CDIM;
    float hi = 0.0f, lo = 0.0f;
#pragma unroll
    for (int c = 0; c < CDIM / 32; c++) {
        float a = zr[lane + 32 * c], b = er[lane + 32 * c];
        float p = __fmul_rn(a, b);
        float perr = fmaf(a, b, -p);
        float s = __fadd_rn(hi, p);
        float bp = __fsub_rn(s, hi);
        float e = __fadd_rn(__fsub_rn(hi, __fsub_rn(s, bp)), __fsub_rn(p, bp));
        hi = s;
        lo = __fadd_rn(lo, __fadd_rn(e, perr));
    }
#pragma unroll
    for (int m = 16; m; m >>= 1) {
        float oh = __shfl_xor_sync(0xffffffffu, hi, m);
        float ol = __shfl_xor_sync(0xffffffffu, lo, m);
        float s = __fadd_rn(hi, oh);
        float bp = __fsub_rn(s, hi);
        float e = __fadd_rn(__fsub_rn(hi, __fsub_rn(s, bp)), __fsub_rn(oh, bp));
        hi = s;
        lo = __fadd_rn(__fadd_rn(lo, ol), e);
    }
    float dotf = __fadd_rn(hi, lo);
    return __fsub_rn(__fadd_rn(g_S[n], g_e2[j]), 2.0f * dotf);
}

// ---------------------------------------------------------------------------
// K1: fused init + transpose/prep + e2 (independent block ranges)
// blocks [0,64): init; [64,576): prep; [576,1600): e2
// ---------------------------------------------------------------------------
__global__ void __launch_bounds__(256) front_kernel(const float* __restrict__ z,
                                                    const float* __restrict__ emb) {
    __shared__ float tile[32][CDIM + 1];
    int bid = blockIdx.x;
    int tid = threadIdx.x;
    if (bid < 64) {
        int i = bid * 256 + tid;
        if (i < NFEAT) g_exkey[i] = ~0ull;
        if (i < KCODE) { g_maxkey[i] = ~0ull; g_hist[i] = 0u; }
        if (i == 0) { g_sse = 0.0f; g_ent = 0.0f; g_util = 0u; g_xcnt = 0u; }
        return;
    }
    int tx = tid & 31, ty = tid >> 5;
    if (bid < 576) {
        int blk = bid - 64;
        int b = blk >> 5, h = blk & 31;
        const float* zp = z + (size_t)b * (CDIM * HDIM * WDIM) + h * WDIM;
#pragma unroll
        for (int i = 0; i < 32; i++) {
            int c = i * 8 + ty;
            tile[tx][c] = zp[c * (HDIM * WDIM) + tx];
        }
        __syncthreads();
        int nbase = b * 1024 + h * 32;
#pragma unroll
        for (int j = 0; j < 4; j++) {
            int w = ty * 4 + j;
            int n = nbase + w;
            float s = 0.0f;
#pragma unroll
            for (int i = 0; i < 8; i++) {
                int c = tx + 32 * i;
                float v = tile[w][c];
                g_zf[(size_t)n * CDIM + c] = v;
                g_zh[(size_t)n * CDIM + c] = __float2half_rn(v);
                s += v * v;
            }
#pragma unroll
            for (int m = 16; m; m >>= 1) s += __shfl_xor_sync(0xffffffffu, s, m);
            if (tx == 0) g_S[n] = s;
        }
        return;
    }
    {
        int j = (bid - 576) * 8 + ty;
        float s = 0.0f;
#pragma unroll
        for (int i = 0; i < 8; i++) {
            float v = emb[(size_t)j * CDIM + tx + 32 * i];
            g_eh[(size_t)j * CDIM + tx + 32 * i] = __float2half_rn(v * ESCALE);
            s += v * v;
        }
#pragma unroll
        for (int m = 16; m; m >>= 1) s += __shfl_xor_sync(0xffffffffu, s, m);
        if (tx == 0) g_e2[j] = s;
    }
}

// ---------------------------------------------------------------------------
// K3: fp16 m16n8k16 GEMM, 256 threads (8 warps 1Mx8N), 2 CTAs/SM.
// Single barrier per k-block; pass-2 early-out via thread-local minima.
// ---------------------------------------------------------------------------
#define SM_ROWKEY 0             // 64 u64  [0,512)
#define SM_COLKEY 512           // 256 u64 [512,2560)
#define SM_SS     2560          // 64 f    [2560,2816)
#define SM_E2S    2816          // 256 f   [2816,3840)
#define SM_DATA   3840
#define STAGE_A   (BM * ROWB)               // 10240
#define STAGE_B   (BN * ROWB)               // 40960
#define STAGE_SZ  (STAGE_A + STAGE_B)       // 51200
#define GEMM_SMEM (SM_DATA + 2 * STAGE_SZ)  // 106240

__device__ __forceinline__ void cpa16(uint32_t dst, const void* src) {
    asm volatile("cp.async.cg.shared.global [%0], [%1], 16;"
                 :: "r"(dst), "l"(src));
}

#define MMA16(d, a0, a1, a2, a3, b0, b1)                                     \
    asm volatile(                                                            \
        "mma.sync.aligned.m16n8k16.row.col.f32.f16.f16.f32 "                 \
        "{%0,%1,%2,%3},{%4,%5,%6,%7},{%8,%9},{%0,%1,%2,%3};"                 \
        : "+f"(d[0]), "+f"(d[1]), "+f"(d[2]), "+f"(d[3])                     \
        : "r"(a0), "r"(a1), "r"(a2), "r"(a3), "r"(b0), "r"(b1))

extern __shared__ char dynsmem[];

__global__ void __launch_bounds__(256, 2)
gemm_mma_kernel(const float* __restrict__ emb) {
    const int tid  = threadIdx.x;
    const int lane = tid & 31;
    const int wn   = tid >> 5;      // warp 0..7 = N split
    const int gid  = lane >> 2;     // 0..7
    const int tig  = lane & 3;      // 0..3
    const int m0   = blockIdx.y * BM;
    const int j0   = blockIdx.x * BN;

    unsigned long long* rowkey = (unsigned long long*)(dynsmem + SM_ROWKEY);
    unsigned long long* colkey = (unsigned long long*)(dynsmem + SM_COLKEY);
    float* Ss  = (float*)(dynsmem + SM_SS);
    float* e2s = (float*)(dynsmem + SM_E2S);

    uint32_t smbase;
    asm("{ .reg .u64 t; cvta.to.shared.u64 t, %1; cvt.u32.u64 %0, t; }"
        : "=r"(smbase) : "l"(dynsmem));

    const int t8 = tid >> 3;            // 0..31
    const int c8 = tid & 7;             // 0..7
    const __half* gA0 = g_zh + (size_t)(m0 + t8) * CDIM + c8 * 8;
    const __half* gB0 = g_eh + (size_t)(j0 + t8) * CDIM + c8 * 8;
    const uint32_t dA0 = smbase + SM_DATA + t8 * ROWB + c8 * 16;
    const uint32_t dB0 = smbase + SM_DATA + STAGE_A + t8 * ROWB + c8 * 16;

    auto load_kb = [&](int s, int kb) {
        uint32_t so = s * STAGE_SZ;
        const __half* ga = gA0 + kb * BK;
        const __half* gb = gB0 + kb * BK;
#pragma unroll
        for (int i = 0; i < 2; i++)
            cpa16(dA0 + so + i * 32 * ROWB, ga + (size_t)i * 32 * CDIM);
#pragma unroll
        for (int i = 0; i < 8; i++)
            cpa16(dB0 + so + i * 32 * ROWB, gb + (size_t)i * 32 * CDIM);
    };

    if (tid < 64) { rowkey[tid] = ~0ull; Ss[tid] = g_S[m0 + tid]; }
    colkey[tid] = ~0ull;
    e2s[tid] = g_e2[j0 + tid];

    load_kb(0, 0);
    asm volatile("cp.async.commit_group;" ::: "memory");

    float acc[4][4][4];
#pragma unroll
    for (int nt = 0; nt < 4; nt++)
#pragma unroll
        for (int mt = 0; mt < 4; mt++)
#pragma unroll
            for (int c = 0; c < 4; c++) acc[nt][mt][c] = 0.0f;

    const int aBase2 = gid * (ROWB / 8) + tig;
    const int bBase2 = (wn * 32 + gid) * (ROWB / 8) + tig;

#pragma unroll 1
    for (int kb = 0; kb < NKB; kb++) {
        asm volatile("cp.async.wait_group 0;" ::: "memory");
        __syncthreads();   // single barrier per k-block

        const uint2* Af2 =
            (const uint2*)(dynsmem + SM_DATA + (kb & 1) * STAGE_SZ);
        const uint2* Bf2 = Af2 + STAGE_A / 8;

#pragma unroll
        for (int ks = 0; ks < BK / 16; ks++) {        // 4 k16-steps
            const int ko = ks * 4;
            uint2 alo[4], ahi[4], bv[4];
#pragma unroll
            for (int mt = 0; mt < 4; mt++) {
                int o = aBase2 + mt * 16 * (ROWB / 8) + ko;
                alo[mt] = Af2[o];
                ahi[mt] = Af2[o + 8 * (ROWB / 8)];
            }
#pragma unroll
            for (int nt = 0; nt < 4; nt++)
                bv[nt] = Bf2[bBase2 + nt * 8 * (ROWB / 8) + ko];
#pragma unroll
            for (int nt = 0; nt < 4; nt++)
#pragma unroll
                for (int mt = 0; mt < 4; mt++)
                    MMA16(acc[nt][mt], alo[mt].x, ahi[mt].x,
                          alo[mt].y, ahi[mt].y, bv[nt].x, bv[nt].y);
            if (ks == 0 && kb + 1 < NKB) {
                load_kb((kb + 1) & 1, kb + 1);
                asm volatile("cp.async.commit_group;" ::: "memory");
            }
        }
    }

    // ---- epilogue pass 1: d -> acc (in place), argmin/argmax ----
    float S_lo[4], S_hi[4];
#pragma unroll
    for (int mt = 0; mt < 4; mt++) {
        S_lo[mt] = Ss[mt * 16 + gid];
        S_hi[mt] = Ss[mt * 16 + gid + 8];
    }
    float bd_lo[4], bd_hi[4];
    int   bj_lo[4], bj_hi[4];
#pragma unroll
    for (int mt = 0; mt < 4; mt++) {
        bd_lo[mt] = __int_as_float(0x7f800000); bj_lo[mt] = 0;
        bd_hi[mt] = __int_as_float(0x7f800000); bj_hi[mt] = 0;
    }

#pragma unroll
    for (int nt = 0; nt < 4; nt++) {
        const int ca = wn * 32 + nt * 8 + 2 * tig;
        const float e2a = e2s[ca], e2b = e2s[ca + 1];
        const int ja = j0 + ca;
        float cva = __int_as_float(0xff800000), cvb = cva;   // -inf
        int cia = 0, cib = 0;
#pragma unroll
        for (int mt = 0; mt < 4; mt++) {
            const int rlo = m0 + mt * 16 + gid;
            float d00 = fmaf(acc[nt][mt][0], DSCALE, S_lo[mt] + e2a);
            float d01 = fmaf(acc[nt][mt][1], DSCALE, S_lo[mt] + e2b);
            float d10 = fmaf(acc[nt][mt][2], DSCALE, S_hi[mt] + e2a);
            float d11 = fmaf(acc[nt][mt][3], DSCALE, S_hi[mt] + e2b);
            acc[nt][mt][0] = d00; acc[nt][mt][1] = d01;
            acc[nt][mt][2] = d10; acc[nt][mt][3] = d11;
            if (d00 < bd_lo[mt]) { bd_lo[mt] = d00; bj_lo[mt] = ja; }
            if (d01 < bd_lo[mt]) { bd_lo[mt] = d01; bj_lo[mt] = ja + 1; }
            if (d10 < bd_hi[mt]) { bd_hi[mt] = d10; bj_hi[mt] = ja; }
            if (d11 < bd_hi[mt]) { bd_hi[mt] = d11; bj_hi[mt] = ja + 1; }
            if (d00 > cva) { cva = d00; cia = rlo; }
            if (d10 > cva) { cva = d10; cia = rlo + 8; }
            if (d01 > cvb) { cvb = d01; cib = rlo; }
            if (d11 > cvb) { cvb = d11; cib = rlo + 8; }
        }
#pragma unroll
        for (int off = 4; off < 32; off <<= 1) {
            float ov = __shfl_xor_sync(0xffffffffu, cva, off);
            int   oi = __shfl_xor_sync(0xffffffffu, cia, off);
            if (ov > cva || (ov == cva && oi < cia)) { cva = ov; cia = oi; }
            ov = __shfl_xor_sync(0xffffffffu, cvb, off);
            oi = __shfl_xor_sync(0xffffffffu, cib, off);
            if (ov > cvb || (ov == cvb && oi < cib)) { cvb = ov; cib = oi; }
        }
        if (gid == 0) {
            atomicMin(&colkey[ca],
                      (((unsigned long long)(~ford(cva))) << 32) | (unsigned)cia);
            atomicMin(&colkey[ca + 1],
                      (((unsigned long long)(~ford(cvb))) << 32) | (unsigned)cib);
        }
    }
#pragma unroll
    for (int mt = 0; mt < 4; mt++) {
        unsigned long long klo =
            (((unsigned long long)ford(bd_lo[mt])) << 32) | (unsigned)bj_lo[mt];
        unsigned long long khi =
            (((unsigned long long)ford(bd_hi[mt])) << 32) | (unsigned)bj_hi[mt];
#pragma unroll
        for (int off = 1; off < 4; off <<= 1) {
            klo = min(klo, __shfl_xor_sync(0xffffffffu, klo, off));
            khi = min(khi, __shfl_xor_sync(0xffffffffu, khi, off));
        }
        if (tig == 0) {
            atomicMin(&rowkey[mt * 16 + gid], klo);
            atomicMin(&rowkey[mt * 16 + gid + 8], khi);
        }
    }
    __syncthreads();

    if (tid < 64) g_blockmin[m0 + tid][blockIdx.x] = rowkey[tid];
    atomicMin(&g_maxkey[j0 + tid], colkey[tid]);

    // ---- epilogue pass 2: append near-tie candidates ----
    // Early-out: bd_lo/bd_hi are the thread-local minima over this thread's
    // 8 distances per row half; if >= threshold, no element can qualify.
#pragma unroll
    for (int mt = 0; mt < 4; mt++) {
        const int rl = mt * 16 + gid;
        const int rh = rl + 8;
        const unsigned long long rkl = rowkey[rl];
        const unsigned long long rkh = rowkey[rh];
        const float vl = unford((unsigned)(rkl >> 32)) + EPSB;
        const float vh = unford((unsigned)(rkh >> 32)) + EPSB;
        if (bd_lo[mt] < vl) {
#pragma unroll
            for (int nt = 0; nt < 4; nt++) {
                const int ca = wn * 32 + nt * 8 + 2 * tig;
                const unsigned ja = (unsigned)(j0 + ca);
                float d00 = acc[nt][mt][0];
                float d01 = acc[nt][mt][1];
                if (d00 < vl) {
                    unsigned long long k =
                        (((unsigned long long)ford(d00)) << 32) | ja;
                    if (k != rkl) {
                        unsigned slot = atomicAdd(&g_xcnt, 1u);
                        if (slot < MAXX)
                            g_extras[slot] = ((unsigned)(m0 + rl) << 13) | ja;
                    }
                }
                if (d01 < vl) {
                    unsigned long long k =
                        (((unsigned long long)ford(d01)) << 32) | (ja + 1);
                    if (k != rkl) {
                        unsigned slot = atomicAdd(&g_xcnt, 1u);
                        if (slot < MAXX)
                            g_extras[slot] = ((unsigned)(m0 + rl) << 13) | (ja + 1);
                    }
                }
            }
        }
        if (bd_hi[mt] < vh) {
#pragma unroll
            for (int nt = 0; nt < 4; nt++) {
                const int ca = wn * 32 + nt * 8 + 2 * tig;
                const unsigned ja = (unsigned)(j0 + ca);
                float d10 = acc[nt][mt][2];
                float d11 = acc[nt][mt][3];
                if (d10 < vh) {
                    unsigned long long k =
                        (((unsigned long long)ford(d10)) << 32) | ja;
                    if (k != rkh) {
                        unsigned slot = atomicAdd(&g_xcnt, 1u);
                        if (slot < MAXX)
                            g_extras[slot] = ((unsigned)(m0 + rh) << 13) | ja;
                    }
                }
                if (d11 < vh) {
                    unsigned long long k =
                        (((unsigned long long)ford(d11)) << 32) | (ja + 1);
                    if (k != rkh) {
                        unsigned slot = atomicAdd(&g_xcnt, 1u);
                        if (slot < MAXX)
                            g_extras[slot] = ((unsigned)(m0 + rh) << 13) | (ja + 1);
                    }
                }
            }
        }
    }
}

// ---------------------------------------------------------------------------
// K4a: exact recompute of appended extras
// ---------------------------------------------------------------------------
__global__ void __launch_bounds__(256) extras_kernel(const float* __restrict__ emb) {
    const unsigned cnt = min(g_xcnt, (unsigned)MAXX);
    const int lane = threadIdx.x & 31;
    const int wid = (blockIdx.x * blockDim.x + threadIdx.x) >> 5;
    const int nw = (gridDim.x * blockDim.x) >> 5;
    for (unsigned i = wid; i < cnt; i += nw) {
        unsigned e = g_extras[i];
        int n = e >> 13;
        int j = e & 8191;
        float d32 = exact_d32(emb, n, j, lane);
        unsigned long long key =
            (((unsigned long long)ford(d32)) << 32) | (unsigned)j;
        if (lane == 0) atomicMin(&g_exkey[n], key);
    }
}

// ---------------------------------------------------------------------------
// K4b: per-row token resolution (+ histogram); NJB==32 -> 1 key per lane
// ---------------------------------------------------------------------------
__global__ void __launch_bounds__(256) tokenfix_kernel(const float* __restrict__ emb) {
    const int lane = threadIdx.x & 31;
    const int wid = (blockIdx.x * blockDim.x + threadIdx.x) >> 5;
    const int nw = (gridDim.x * blockDim.x) >> 5;
    for (int n = wid; n < NFEAT; n += nw) {
        unsigned long long k = g_blockmin[n][lane];   // NJB == 32
        unsigned long long gm = k;
#pragma unroll
        for (int m = 16; m; m >>= 1)
            gm = min(gm, __shfl_xor_sync(0xffffffffu, gm, m));
        float thresh = unford((unsigned)(gm >> 32)) + EPSB;
        bool cand = unford((unsigned)(k >> 32)) < thresh;
        unsigned bal = __ballot_sync(0xffffffffu, cand);
        unsigned long long ex = g_exkey[n];
        unsigned tok;
        if (__popc(bal) == 1 && ex == ~0ull) {
            tok = (unsigned)(gm & 0xffffffffull);
        } else {
            unsigned long long best = ex;
            unsigned b = bal;
            while (b) {
                int src = __ffs(b) - 1;
                b &= b - 1;
                unsigned jj = __shfl_sync(0xffffffffu,
                                          (unsigned)(k & 0xffffffffull), src);
                float d32 = exact_d32(emb, n, (int)jj, lane);
                unsigned long long key =
                    (((unsigned long long)ford(d32)) << 32) | jj;
                best = min(best, key);
            }
            tok = (unsigned)(best & 0xffffffffull);
        }
        if (lane == 0) {
            g_token[n] = (int)tok;
            atomicAdd(&g_hist[tok], 1u);
        }
    }
}

// ---------------------------------------------------------------------------
// K5: fused z_q output + SSE (blocks [0,512)) and per-code update (rest)
// ---------------------------------------------------------------------------
__global__ void __launch_bounds__(256) back_kernel(const float* __restrict__ emb,
                                                   const float* __restrict__ eprob,
                                                   float* __restrict__ out) {
    __shared__ float rowbuf[32][CDIM + 1];
    __shared__ int stok[32];
    __shared__ float red[8];
    int bid = blockIdx.x;
    int tid = threadIdx.x;
    if (bid < 512) {
        int b = bid >> 5, h = bid & 31;
        int nbase = b * 1024 + h * 32;
        if (tid < 32) stok[tid] = g_token[nbase + tid];
        __syncthreads();
        float acc = 0.0f;
#pragma unroll 4
        for (int w = 0; w < 32; w++) {
            float v  = emb[(size_t)stok[w] * CDIM + tid];
            float zv = g_zf[(size_t)(nbase + w) * CDIM + tid];
            float diff = __fsub_rn(v, zv);
            acc = fmaf(diff, diff, acc);
            rowbuf[w][tid] = __fadd_rn(zv, diff);
        }
        float s = acc;
#pragma unroll
        for (int m = 16; m; m >>= 1) s += __shfl_xor_sync(0xffffffffu, s, m);
        if ((tid & 31) == 0) red[tid >> 5] = s;
        __syncthreads();
        if (tid == 0) {
            float t = 0.0f;
#pragma unroll
            for (int i = 0; i < 8; i++) t += red[i];
            atomicAdd(&g_sse, t);
        }
        int tx = tid & 31, ty = tid >> 5;
#pragma unroll
        for (int i = 0; i < 32; i++) {
            int c = i * 8 + ty;
            out[OUT_ZQ + (((size_t)b * CDIM + c) * HDIM + h) * WDIM + tx] =
                rowbuf[tx][c];
        }
        return;
    }
    {
        int j = bid - 512;
        int c = tid;
        unsigned hcnt = g_hist[j];
        float avg = (float)hcnt * (1.0f / 16384.0f);
        float np  = __fadd_rn(__fmul_rn(eprob[j], 0.99f), __fmul_rn(avg, 0.01f));
        float t = __fmul_rn(np, 8192.0f);
        t = __fmul_rn(t, 10.0f);
        t = __fdiv_rn(t, 0.01f);
        float decay = expf(-t - 0.001f);
        float omd = __fsub_rn(1.0f, decay);
        if (c == 0) {
            out[OUT_NPROB + j] = np;
            atomicAdd(&g_ent, avg * logf(avg + 1e-10f));
            if (hcnt > 0) atomicAdd(&g_util, 1u);
        }
        int fi = (int)(g_maxkey[j] & 0xffffffffull);
        float rf = g_zf[(size_t)fi * CDIM + c];
        float e  = emb[(size_t)j * CDIM + c];
        out[OUT_NEMB + (size_t)j * CDIM + c] =
            __fadd_rn(__fmul_rn(e, omd), __fmul_rn(rf, decay));
    }
}

// ---------------------------------------------------------------------------
__global__ void fin_kernel(float* __restrict__ out) {
    float sse = g_sse;
    float mse = sse / 4194304.0f;
    out[OUT_LOSS] = __fadd_rn(__fmul_rn(0.25f, mse), mse);
    out[OUT_QERR] = sse / 16384.0f;
    out[OUT_UTIL] = (float)g_util / 8192.0f;
    out[OUT_PERP] = expf(-g_ent);
}

// ---------------------------------------------------------------------------
extern "C" void kernel_launch(void* const* d_in, const int* in_sizes, int n_in,
                              void* d_out, int out_size) {
    (void)in_sizes; (void)n_in; (void)out_size;
    const float* z     = (const float*)d_in[0];
    const float* emb   = (const float*)d_in[1];
    const float* eprob = (const float*)d_in[2];
    float* out = (float*)d_out;

    static int smem_set = 0;
    if (!smem_set) {
        cudaFuncSetAttribute(gemm_mma_kernel,
                             cudaFuncAttributeMaxDynamicSharedMemorySize,
                             GEMM_SMEM);
        smem_set = 1;
    }

    front_kernel<<<1600, 256>>>(z, emb);
    gemm_mma_kernel<<<dim3(NJB, NFEAT / BM), 256, GEMM_SMEM>>>(emb);
    extras_kernel<<<1024, 256>>>(emb);
    tokenfix_kernel<<<2048, 256>>>(emb);
    back_kernel<<<512 + KCODE, 256>>>(emb, eprob, out);
    fin_kernel<<<1, 1>>>(out);
}

// round 16
// speedup vs baseline: 1.0104x; 1.0014x over previous
#include <cuda_runtime.h>
#include <cuda_fp16.h>
#include <math.h>
#include <stdint.h>

// Problem constants
#define NFEAT 16384          // B*H*W = 16*32*32
#define KCODE 8192           // codebook size
#define CDIM  256            // codebook dim
#define BATCH 16
#define HDIM  32
#define WDIM  32

// Output layout (float32, concatenated in reference tuple order)
#define OUT_ZQ    0
#define OUT_LOSS  4194304
#define OUT_QERR  4194305
#define OUT_UTIL  4194306
#define OUT_PERP  4194307
#define OUT_NEMB  4194308
#define OUT_NPROB 6291460

// GEMM tiling (fp16 m16n8k16; BM64 x BN256, 256 thr, 2 CTAs/SM)
#define BM 64
#define BN 256
#define NJB (KCODE / BN)     // 32 j-blocks
#define BK 64                // fp16 k-chunk per stage
#define NKB (CDIM / BK)      // 4
#define ROWB 160             // 80 halves per row (padded) -> conflict-free LDS.64

// codebook pre-scale 2^14 (exact); epilogue rescale -2*2^-14 = -2^-13
#define ESCALE 16384.0f
#define DSCALE (-1.0f / 8192.0f)

// candidate window: > 2*ulp(256) + 2*fp16_approx_err
#define EPSB 1.2e-4f
#define MAXX (1 << 21)

// Scratch (device globals; no dynamic allocation allowed)
__device__ float              g_zf[NFEAT * CDIM];
__device__ __half             g_zh[NFEAT * CDIM];
__device__ __half             g_eh[KCODE * CDIM];   // embedding * 2^14, fp16
__device__ float              g_S[NFEAT];
__device__ float              g_e2[KCODE];
__device__ unsigned long long g_blockmin[NFEAT][NJB];
__device__ unsigned long long g_exkey[NFEAT];
__device__ unsigned int       g_extras[MAXX];
__device__ unsigned int       g_xcnt;
__device__ unsigned long long g_maxkey[KCODE];
__device__ unsigned int       g_hist[KCODE];
__device__ int                g_token[NFEAT];
__device__ float              g_sse;
__device__ float              g_ent;
__device__ unsigned int       g_util;

__device__ __forceinline__ unsigned int ford(float f) {
    unsigned int u = __float_as_uint(f);
    return u ^ ((((int)u) >> 31) | 0x80000000u);
}
__device__ __forceinline__ float unford(unsigned int u) {
    unsigned int v = (u & 0x80000000u) ? (u ^ 0x80000000u) : ~u;
    return __uint_as_float(v);
}

// exact distance on the reference fp32 grid, via compensated fp32 dot.
__device__ __forceinline__ float exact_d32(const float* __restrict__ emb,
                                           int n, int j, int lane) {
    const float* zr = g_zf + (size_t)n * CDIM;
    const float* er = emb + (size_t)j * CDIM;
    float hi = 0.0f, lo = 0.0f;
#pragma unroll
    for (int c = 0; c < CDIM / 32; c++) {
        float a = zr[lane + 32 * c], b = er[lane + 32 * c];
        float p = __fmul_rn(a, b);
        float perr = fmaf(a, b, -p);
        float s = __fadd_rn(hi, p);
        float bp = __fsub_rn(s, hi);
        float e = __fadd_rn(__fsub_rn(hi, __fsub_rn(s, bp)), __fsub_rn(p, bp));
        hi = s;
        lo = __fadd_rn(lo, __fadd_rn(e, perr));
    }
#pragma unroll
    for (int m = 16; m; m >>= 1) {
        float oh = __shfl_xor_sync(0xffffffffu, hi, m);
        float ol = __shfl_xor_sync(0xffffffffu, lo, m);
        float s = __fadd_rn(hi, oh);
        float bp = __fsub_rn(s, hi);
        float e = __fadd_rn(__fsub_rn(hi, __fsub_rn(s, bp)), __fsub_rn(oh, bp));
        hi = s;
        lo = __fadd_rn(__fadd_rn(lo, ol), e);
    }
    float dotf = __fadd_rn(hi, lo);
    return __fsub_rn(__fadd_rn(g_S[n], g_e2[j]), 2.0f * dotf);
}

// ---------------------------------------------------------------------------
// K1: fused init + transpose/prep + e2 (independent block ranges)
// blocks [0,64): init; [64,576): prep; [576,1600): e2
// ---------------------------------------------------------------------------
__global__ void __launch_bounds__(256) front_kernel(const float* __restrict__ z,
                                                    const float* __restrict__ emb) {
    __shared__ float tile[32][CDIM + 1];
    int bid = blockIdx.x;
    int tid = threadIdx.x;
    if (bid < 64) {
        int i = bid * 256 + tid;
        if (i < NFEAT) g_exkey[i] = ~0ull;
        if (i < KCODE) { g_maxkey[i] = ~0ull; g_hist[i] = 0u; }
        if (i == 0) { g_sse = 0.0f; g_ent = 0.0f; g_util = 0u; g_xcnt = 0u; }
        return;
    }
    int tx = tid & 31, ty = tid >> 5;
    if (bid < 576) {
        int blk = bid - 64;
        int b = blk >> 5, h = blk & 31;
        const float* zp = z + (size_t)b * (CDIM * HDIM * WDIM) + h * WDIM;
#pragma unroll
        for (int i = 0; i < 32; i++) {
            int c = i * 8 + ty;
            tile[tx][c] = zp[c * (HDIM * WDIM) + tx];
        }
        __syncthreads();
        int nbase = b * 1024 + h * 32;
#pragma unroll
        for (int j = 0; j < 4; j++) {
            int w = ty * 4 + j;
            int n = nbase + w;
            float s = 0.0f;
#pragma unroll
            for (int i = 0; i < 8; i++) {
                int c = tx + 32 * i;
                float v = tile[w][c];
                g_zf[(size_t)n * CDIM + c] = v;
                g_zh[(size_t)n * CDIM + c] = __float2half_rn(v);
                s += v * v;
            }
#pragma unroll
            for (int m = 16; m; m >>= 1) s += __shfl_xor_sync(0xffffffffu, s, m);
            if (tx == 0) g_S[n] = s;
        }
        return;
    }
    {
        int j = (bid - 576) * 8 + ty;
        float s = 0.0f;
#pragma unroll
        for (int i = 0; i < 8; i++) {
            float v = emb[(size_t)j * CDIM + tx + 32 * i];
            g_eh[(size_t)j * CDIM + tx + 32 * i] = __float2half_rn(v * ESCALE);
            s += v * v;
        }
#pragma unroll
        for (int m = 16; m; m >>= 1) s += __shfl_xor_sync(0xffffffffu, s, m);
        if (tx == 0) g_e2[j] = s;
    }
}

// ---------------------------------------------------------------------------
// K3: fp16 m16n8k16 GEMM, 256 threads (8 warps 1Mx8N), 2 CTAs/SM.
// Single barrier per k-block; pass-2 early-out; value-only column-max with
// bit-equality index recovery (all in registers).
// ---------------------------------------------------------------------------
#define SM_ROWKEY 0             // 64 u64  [0,512)
#define SM_COLKEY 512           // 256 u64 [512,2560)
#define SM_SS     2560          // 64 f    [2560,2816)
#define SM_E2S    2816          // 256 f   [2816,3840)
#define SM_DATA   3840
#define STAGE_A   (BM * ROWB)               // 10240
#define STAGE_B   (BN * ROWB)               // 40960
#define STAGE_SZ  (STAGE_A + STAGE_B)       // 51200
#define GEMM_SMEM (SM_DATA + 2 * STAGE_SZ)  // 106240

__device__ __forceinline__ void cpa16(uint32_t dst, const void* src) {
    asm volatile("cp.async.cg.shared.global [%0], [%1], 16;"
                 :: "r"(dst), "l"(src));
}

#define MMA16(d, a0, a1, a2, a3, b0, b1)                                     \
    asm volatile(                                                            \
        "mma.sync.aligned.m16n8k16.row.col.f32.f16.f16.f32 "                 \
        "{%0,%1,%2,%3},{%4,%5,%6,%7},{%8,%9},{%0,%1,%2,%3};"                 \
        : "+f"(d[0]), "+f"(d[1]), "+f"(d[2]), "+f"(d[3])                     \
        : "r"(a0), "r"(a1), "r"(a2), "r"(a3), "r"(b0), "r"(b1))

extern __shared__ char dynsmem[];

__global__ void __launch_bounds__(256, 2)
gemm_mma_kernel(const float* __restrict__ emb) {
    const int tid  = threadIdx.x;
    const int lane = tid & 31;
    const int wn   = tid >> 5;      // warp 0..7 = N split
    const int gid  = lane >> 2;     // 0..7
    const int tig  = lane & 3;      // 0..3
    const int m0   = blockIdx.y * BM;
    const int j0   = blockIdx.x * BN;

    unsigned long long* rowkey = (unsigned long long*)(dynsmem + SM_ROWKEY);
    unsigned long long* colkey = (unsigned long long*)(dynsmem + SM_COLKEY);
    float* Ss  = (float*)(dynsmem + SM_SS);
    float* e2s = (float*)(dynsmem + SM_E2S);

    uint32_t smbase;
    asm("{ .reg .u64 t; cvta.to.shared.u64 t, %1; cvt.u32.u64 %0, t; }"
        : "=r"(smbase) : "l"(dynsmem));

    const int t8 = tid >> 3;            // 0..31
    const int c8 = tid & 7;             // 0..7
    const __half* gA0 = g_zh + (size_t)(m0 + t8) * CDIM + c8 * 8;
    const __half* gB0 = g_eh + (size_t)(j0 + t8) * CDIM + c8 * 8;
    const uint32_t dA0 = smbase + SM_DATA + t8 * ROWB + c8 * 16;
    const uint32_t dB0 = smbase + SM_DATA + STAGE_A + t8 * ROWB + c8 * 16;

    auto load_kb = [&](int s, int kb) {
        uint32_t so = s * STAGE_SZ;
        const __half* ga = gA0 + kb * BK;
        const __half* gb = gB0 + kb * BK;
#pragma unroll
        for (int i = 0; i < 2; i++)
            cpa16(dA0 + so + i * 32 * ROWB, ga + (size_t)i * 32 * CDIM);
#pragma unroll
        for (int i = 0; i < 8; i++)
            cpa16(dB0 + so + i * 32 * ROWB, gb + (size_t)i * 32 * CDIM);
    };

    if (tid < 64) { rowkey[tid] = ~0ull; Ss[tid] = g_S[m0 + tid]; }
    colkey[tid] = ~0ull;
    e2s[tid] = g_e2[j0 + tid];

    load_kb(0, 0);
    asm volatile("cp.async.commit_group;" ::: "memory");

    float acc[4][4][4];
#pragma unroll
    for (int nt = 0; nt < 4; nt++)
#pragma unroll
        for (int mt = 0; mt < 4; mt++)
#pragma unroll
            for (int c = 0; c < 4; c++) acc[nt][mt][c] = 0.0f;

    const int aBase2 = gid * (ROWB / 8) + tig;
    const int bBase2 = (wn * 32 + gid) * (ROWB / 8) + tig;

#pragma unroll 1
    for (int kb = 0; kb < NKB; kb++) {
        asm volatile("cp.async.wait_group 0;" ::: "memory");
        __syncthreads();   // single barrier per k-block

        const uint2* Af2 =
            (const uint2*)(dynsmem + SM_DATA + (kb & 1) * STAGE_SZ);
        const uint2* Bf2 = Af2 + STAGE_A / 8;

#pragma unroll
        for (int ks = 0; ks < BK / 16; ks++) {        // 4 k16-steps
            const int ko = ks * 4;
            uint2 alo[4], ahi[4], bv[4];
#pragma unroll
            for (int mt = 0; mt < 4; mt++) {
                int o = aBase2 + mt * 16 * (ROWB / 8) + ko;
                alo[mt] = Af2[o];
                ahi[mt] = Af2[o + 8 * (ROWB / 8)];
            }
#pragma unroll
            for (int nt = 0; nt < 4; nt++)
                bv[nt] = Bf2[bBase2 + nt * 8 * (ROWB / 8) + ko];
#pragma unroll
            for (int nt = 0; nt < 4; nt++)
#pragma unroll
                for (int mt = 0; mt < 4; mt++)
                    MMA16(acc[nt][mt], alo[mt].x, ahi[mt].x,
                          alo[mt].y, ahi[mt].y, bv[nt].x, bv[nt].y);
            if (ks == 0 && kb + 1 < NKB) {
                load_kb((kb + 1) & 1, kb + 1);
                asm volatile("cp.async.commit_group;" ::: "memory");
            }
        }
    }

    // ---- epilogue pass 1: d -> acc (in place), argmin/argmax ----
    float S_lo[4], S_hi[4];
#pragma unroll
    for (int mt = 0; mt < 4; mt++) {
        S_lo[mt] = Ss[mt * 16 + gid];
        S_hi[mt] = Ss[mt * 16 + gid + 8];
    }
    float bd_lo[4], bd_hi[4];
    int   bj_lo[4], bj_hi[4];
#pragma unroll
    for (int mt = 0; mt < 4; mt++) {
        bd_lo[mt] = __int_as_float(0x7f800000); bj_lo[mt] = 0;
        bd_hi[mt] = __int_as_float(0x7f800000); bj_hi[mt] = 0;
    }

#pragma unroll
    for (int nt = 0; nt < 4; nt++) {
        const int ca = wn * 32 + nt * 8 + 2 * tig;
        const float e2a = e2s[ca], e2b = e2s[ca + 1];
        const int ja = j0 + ca;
        float cva = __int_as_float(0xff800000), cvb = cva;   // -inf
#pragma unroll
        for (int mt = 0; mt < 4; mt++) {
            float d00 = fmaf(acc[nt][mt][0], DSCALE, S_lo[mt] + e2a);
            float d01 = fmaf(acc[nt][mt][1], DSCALE, S_lo[mt] + e2b);
            float d10 = fmaf(acc[nt][mt][2], DSCALE, S_hi[mt] + e2a);
            float d11 = fmaf(acc[nt][mt][3], DSCALE, S_hi[mt] + e2b);
            acc[nt][mt][0] = d00; acc[nt][mt][1] = d01;
            acc[nt][mt][2] = d10; acc[nt][mt][3] = d11;
            if (d00 < bd_lo[mt]) { bd_lo[mt] = d00; bj_lo[mt] = ja; }
            if (d01 < bd_lo[mt]) { bd_lo[mt] = d01; bj_lo[mt] = ja + 1; }
            if (d10 < bd_hi[mt]) { bd_hi[mt] = d10; bj_hi[mt] = ja; }
            if (d11 < bd_hi[mt]) { bd_hi[mt] = d11; bj_hi[mt] = ja + 1; }
            cva = fmaxf(cva, d00); cva = fmaxf(cva, d10);
            cvb = fmaxf(cvb, d01); cvb = fmaxf(cvb, d11);
        }
        // warp max over gid lanes (value only)
#pragma unroll
        for (int off = 4; off < 32; off <<= 1) {
            cva = fmaxf(cva, __shfl_xor_sync(0xffffffffu, cva, off));
            cvb = fmaxf(cvb, __shfl_xor_sync(0xffffffffu, cvb, off));
        }
        // index recovery: bit-equality vs warp max, min row wins
        int ria = 0x7fffffff, rib = 0x7fffffff;
#pragma unroll
        for (int mt = 0; mt < 4; mt++) {
            const int rlo = m0 + mt * 16 + gid;
            if (acc[nt][mt][0] == cva) ria = min(ria, rlo);
            if (acc[nt][mt][2] == cva) ria = min(ria, rlo + 8);
            if (acc[nt][mt][1] == cvb) rib = min(rib, rlo);
            if (acc[nt][mt][3] == cvb) rib = min(rib, rlo + 8);
        }
#pragma unroll
        for (int off = 4; off < 32; off <<= 1) {
            ria = min(ria, __shfl_xor_sync(0xffffffffu, ria, off));
            rib = min(rib, __shfl_xor_sync(0xffffffffu, rib, off));
        }
        if (gid == 0) {
            atomicMin(&colkey[ca],
                      (((unsigned long long)(~ford(cva))) << 32) | (unsigned)ria);
            atomicMin(&colkey[ca + 1],
                      (((unsigned long long)(~ford(cvb))) << 32) | (unsigned)rib);
        }
    }
#pragma unroll
    for (int mt = 0; mt < 4; mt++) {
        unsigned long long klo =
            (((unsigned long long)ford(bd_lo[mt])) << 32) | (unsigned)bj_lo[mt];
        unsigned long long khi =
            (((unsigned long long)ford(bd_hi[mt])) << 32) | (unsigned)bj_hi[mt];
#pragma unroll
        for (int off = 1; off < 4; off <<= 1) {
            klo = min(klo, __shfl_xor_sync(0xffffffffu, klo, off));
            khi = min(khi, __shfl_xor_sync(0xffffffffu, khi, off));
        }
        if (tig == 0) {
            atomicMin(&rowkey[mt * 16 + gid], klo);
            atomicMin(&rowkey[mt * 16 + gid + 8], khi);
        }
    }
    __syncthreads();

    if (tid < 64) g_blockmin[m0 + tid][blockIdx.x] = rowkey[tid];
    atomicMin(&g_maxkey[j0 + tid], colkey[tid]);

    // ---- epilogue pass 2: append near-tie candidates (early-out) ----
#pragma unroll
    for (int mt = 0; mt < 4; mt++) {
        const int rl = mt * 16 + gid;
        const int rh = rl + 8;
        const unsigned long long rkl = rowkey[rl];
        const unsigned long long rkh = rowkey[rh];
        const float vl = unford((unsigned)(rkl >> 32)) + EPSB;
        const float vh = unford((unsigned)(rkh >> 32)) + EPSB;
        if (bd_lo[mt] < vl) {
#pragma unroll
            for (int nt = 0; nt < 4; nt++) {
                const int ca = wn * 32 + nt * 8 + 2 * tig;
                const unsigned ja = (unsigned)(j0 + ca);
                float d00 = acc[nt][mt][0];
                float d01 = acc[nt][mt][1];
                if (d00 < vl) {
                    unsigned long long k =
                        (((unsigned long long)ford(d00)) << 32) | ja;
                    if (k != rkl) {
                        unsigned slot = atomicAdd(&g_xcnt, 1u);
                        if (slot < MAXX)
                            g_extras[slot] = ((unsigned)(m0 + rl) << 13) | ja;
                    }
                }
                if (d01 < vl) {
                    unsigned long long k =
                        (((unsigned long long)ford(d01)) << 32) | (ja + 1);
                    if (k != rkl) {
                        unsigned slot = atomicAdd(&g_xcnt, 1u);
                        if (slot < MAXX)
                            g_extras[slot] = ((unsigned)(m0 + rl) << 13) | (ja + 1);
                    }
                }
            }
        }
        if (bd_hi[mt] < vh) {
#pragma unroll
            for (int nt = 0; nt < 4; nt++) {
                const int ca = wn * 32 + nt * 8 + 2 * tig;
                const unsigned ja = (unsigned)(j0 + ca);
                float d10 = acc[nt][mt][2];
                float d11 = acc[nt][mt][3];
                if (d10 < vh) {
                    unsigned long long k =
                        (((unsigned long long)ford(d10)) << 32) | ja;
                    if (k != rkh) {
                        unsigned slot = atomicAdd(&g_xcnt, 1u);
                        if (slot < MAXX)
                            g_extras[slot] = ((unsigned)(m0 + rh) << 13) | ja;
                    }
                }
                if (d11 < vh) {
                    unsigned long long k =
                        (((unsigned long long)ford(d11)) << 32) | (ja + 1);
                    if (k != rkh) {
                        unsigned slot = atomicAdd(&g_xcnt, 1u);
                        if (slot < MAXX)
                            g_extras[slot] = ((unsigned)(m0 + rh) << 13) | (ja + 1);
                    }
                }
            }
        }
    }
}

// ---------------------------------------------------------------------------
// K4a: exact recompute of appended extras
// ---------------------------------------------------------------------------
__global__ void __launch_bounds__(256) extras_kernel(const float* __restrict__ emb) {
    const unsigned cnt = min(g_xcnt, (unsigned)MAXX);
    const int lane = threadIdx.x & 31;
    const int wid = (blockIdx.x * blockDim.x + threadIdx.x) >> 5;
    const int nw = (gridDim.x * blockDim.x) >> 5;
    for (unsigned i = wid; i < cnt; i += nw) {
        unsigned e = g_extras[i];
        int n = e >> 13;
        int j = e & 8191;
        float d32 = exact_d32(emb, n, j, lane);
        unsigned long long key =
            (((unsigned long long)ford(d32)) << 32) | (unsigned)j;
        if (lane == 0) atomicMin(&g_exkey[n], key);
    }
}

// ---------------------------------------------------------------------------
// K4b: per-row token resolution (+ histogram); NJB==32 -> 1 key per lane
// ---------------------------------------------------------------------------
__global__ void __launch_bounds__(256) tokenfix_kernel(const float* __restrict__ emb) {
    const int lane = threadIdx.x & 31;
    const int wid = (blockIdx.x * blockDim.x + threadIdx.x) >> 5;
    const int nw = (gridDim.x * blockDim.x) >> 5;
    for (int n = wid; n < NFEAT; n += nw) {
        unsigned long long k = g_blockmin[n][lane];   // NJB == 32
        unsigned long long gm = k;
#pragma unroll
        for (int m = 16; m; m >>= 1)
            gm = min(gm, __shfl_xor_sync(0xffffffffu, gm, m));
        float thresh = unford((unsigned)(gm >> 32)) + EPSB;
        bool cand = unford((unsigned)(k >> 32)) < thresh;
        unsigned bal = __ballot_sync(0xffffffffu, cand);
        unsigned long long ex = g_exkey[n];
        unsigned tok;
        if (__popc(bal) == 1 && ex == ~0ull) {
            tok = (unsigned)(gm & 0xffffffffull);
        } else {
            unsigned long long best = ex;
            unsigned b = bal;
            while (b) {
                int src = __ffs(b) - 1;
                b &= b - 1;
                unsigned jj = __shfl_sync(0xffffffffu,
                                          (unsigned)(k & 0xffffffffull), src);
                float d32 = exact_d32(emb, n, (int)jj, lane);
                unsigned long long key =
                    (((unsigned long long)ford(d32)) << 32) | jj;
                best = min(best, key);
            }
            tok = (unsigned)(best & 0xffffffffull);
        }
        if (lane == 0) {
            g_token[n] = (int)tok;
            atomicAdd(&g_hist[tok], 1u);
        }
    }
}

// ---------------------------------------------------------------------------
// K5: fused z_q output + SSE (blocks [0,512)) and per-code update (rest)
// ---------------------------------------------------------------------------
__global__ void __launch_bounds__(256) back_kernel(const float* __restrict__ emb,
                                                   const float* __restrict__ eprob,
                                                   float* __restrict__ out) {
    __shared__ float rowbuf[32][CDIM + 1];
    __shared__ int stok[32];
    __shared__ float red[8];
    int bid = blockIdx.x;
    int tid = threadIdx.x;
    if (bid < 512) {
        int b = bid >> 5, h = bid & 31;
        int nbase = b * 1024 + h * 32;
        if (tid < 32) stok[tid] = g_token[nbase + tid];
        __syncthreads();
        float acc = 0.0f;
#pragma unroll 4
        for (int w = 0; w < 32; w++) {
            float v  = emb[(size_t)stok[w] * CDIM + tid];
            float zv = g_zf[(size_t)(nbase + w) * CDIM + tid];
            float diff = __fsub_rn(v, zv);
            acc = fmaf(diff, diff, acc);
            rowbuf[w][tid] = __fadd_rn(zv, diff);
        }
        float s = acc;
#pragma unroll
        for (int m = 16; m; m >>= 1) s += __shfl_xor_sync(0xffffffffu, s, m);
        if ((tid & 31) == 0) red[tid >> 5] = s;
        __syncthreads();
        if (tid == 0) {
            float t = 0.0f;
#pragma unroll
            for (int i = 0; i < 8; i++) t += red[i];
            atomicAdd(&g_sse, t);
        }
        int tx = tid & 31, ty = tid >> 5;
#pragma unroll
        for (int i = 0; i < 32; i++) {
            int c = i * 8 + ty;
            out[OUT_ZQ + (((size_t)b * CDIM + c) * HDIM + h) * WDIM + tx] =
                rowbuf[tx][c];
        }
        return;
    }
    {
        int j = bid - 512;
        int c = tid;
        unsigned hcnt = g_hist[j];
        float avg = (float)hcnt * (1.0f / 16384.0f);
        float np  = __fadd_rn(__fmul_rn(eprob[j], 0.99f), __fmul_rn(avg, 0.01f));
        float t = __fmul_rn(np, 8192.0f);
        t = __fmul_rn(t, 10.0f);
        t = __fdiv_rn(t, 0.01f);
        float decay = expf(-t - 0.001f);
        float omd = __fsub_rn(1.0f, decay);
        if (c == 0) {
            out[OUT_NPROB + j] = np;
            atomicAdd(&g_ent, avg * logf(avg + 1e-10f));
            if (hcnt > 0) atomicAdd(&g_util, 1u);
        }
        int fi = (int)(g_maxkey[j] & 0xffffffffull);
        float rf = g_zf[(size_t)fi * CDIM + c];
        float e  = emb[(size_t)j * CDIM + c];
        out[OUT_NEMB + (size_t)j * CDIM + c] =
            __fadd_rn(__fmul_rn(e, omd), __fmul_rn(rf, decay));
    }
}

// ---------------------------------------------------------------------------
__global__ void fin_kernel(float* __restrict__ out) {
    float sse = g_sse;
    float mse = sse / 4194304.0f;
    out[OUT_LOSS] = __fadd_rn(__fmul_rn(0.25f, mse), mse);
    out[OUT_QERR] = sse / 16384.0f;
    out[OUT_UTIL] = (float)g_util / 8192.0f;
    out[OUT_PERP] = expf(-g_ent);
}

// ---------------------------------------------------------------------------
extern "C" void kernel_launch(void* const* d_in, const int* in_sizes, int n_in,
                              void* d_out, int out_size) {
    (void)in_sizes; (void)n_in; (void)out_size;
    const float* z     = (const float*)d_in[0];
    const float* emb   = (const float*)d_in[1];
    const float* eprob = (const float*)d_in[2];
    float* out = (float*)d_out;

    static int smem_set = 0;
    if (!smem_set) {
        cudaFuncSetAttribute(gemm_mma_kernel,
                             cudaFuncAttributeMaxDynamicSharedMemorySize,
                             GEMM_SMEM);
        smem_set = 1;
    }

    front_kernel<<<1600, 256>>>(z, emb);
    gemm_mma_kernel<<<dim3(NJB, NFEAT / BM), 256, GEMM_SMEM>>>(emb);
    extras_kernel<<<1024, 256>>>(emb);
    tokenfix_kernel<<<2048, 256>>>(emb);
    back_kernel<<<512 + KCODE, 256>>>(emb, eprob, out);
    fin_kernel<<<1, 1>>>(out);
}

// round 17
// speedup vs baseline: 1.0114x; 1.0010x over previous
#include <cuda_runtime.h>
#include <cuda_fp16.h>
#include <math.h>
#include <stdint.h>

// Problem constants
#define NFEAT 16384          // B*H*W = 16*32*32
#define KCODE 8192           // codebook size
#define CDIM  256            // codebook dim
#define BATCH 16
#define HDIM  32
#define WDIM  32

// Output layout (float32, concatenated in reference tuple order)
#define OUT_ZQ    0
#define OUT_LOSS  4194304
#define OUT_QERR  4194305
#define OUT_UTIL  4194306
#define OUT_PERP  4194307
#define OUT_NEMB  4194308
#define OUT_NPROB 6291460

// GEMM tiling (fp16 m16n8k16; BM64 x BN256, 256 thr, 2 CTAs/SM)
#define BM 64
#define BN 256
#define NJB (KCODE / BN)     // 32 j-blocks
#define BK 64                // fp16 k-chunk per stage
#define NKB (CDIM / BK)      // 4
#define ROWB 160             // 80 halves per row (padded) -> conflict-free LDS.64

// codebook pre-scale 2^14 (exact); epilogue rescale -2*2^-14 = -2^-13
#define ESCALE 16384.0f
#define DSCALE (-1.0f / 8192.0f)

// candidate window: > 2*ulp(256) + 2*fp16_approx_err
#define EPSB 1.2e-4f
#define MAXX (1 << 21)

// Scratch (device globals; no dynamic allocation allowed)
__device__ float              g_zf[NFEAT * CDIM];
__device__ __half             g_zh[NFEAT * CDIM];
__device__ __half             g_eh[KCODE * CDIM];   // embedding * 2^14, fp16
__device__ float              g_S[NFEAT];
__device__ float              g_e2[KCODE];
__device__ unsigned long long g_blockmin[NFEAT][NJB];
__device__ unsigned long long g_exkey[NFEAT];
__device__ unsigned int       g_extras[MAXX];
__device__ unsigned int       g_xcnt;
__device__ unsigned long long g_maxkey[KCODE];
__device__ unsigned int       g_hist[KCODE];
__device__ int                g_token[NFEAT];
__device__ float              g_sse;
__device__ float              g_ent;
__device__ unsigned int       g_util;

__device__ __forceinline__ unsigned int ford(float f) {
    unsigned int u = __float_as_uint(f);
    return u ^ ((((int)u) >> 31) | 0x80000000u);
}
__device__ __forceinline__ float unford(unsigned int u) {
    unsigned int v = (u & 0x80000000u) ? (u ^ 0x80000000u) : ~u;
    return __uint_as_float(v);
}

// exact distance on the reference fp32 grid, via compensated fp32 dot.
__device__ __forceinline__ float exact_d32(const float* __restrict__ emb,
                                           int n, int j, int lane) {
    const float* zr = g_zf + (size_t)n * CDIM;
    const float* er = emb + (size_t)j * CDIM;
    float hi = 0.0f, lo = 0.0f;
#pragma unroll
    for (int c = 0; c < CDIM / 32; c++) {
        float a = zr[lane + 32 * c], b = er[lane + 32 * c];
        float p = __fmul_rn(a, b);
        float perr = fmaf(a, b, -p);
        float s = __fadd_rn(hi, p);
        float bp = __fsub_rn(s, hi);
        float e = __fadd_rn(__fsub_rn(hi, __fsub_rn(s, bp)), __fsub_rn(p, bp));
        hi = s;
        lo = __fadd_rn(lo, __fadd_rn(e, perr));
    }
#pragma unroll
    for (int m = 16; m; m >>= 1) {
        float oh = __shfl_xor_sync(0xffffffffu, hi, m);
        float ol = __shfl_xor_sync(0xffffffffu, lo, m);
        float s = __fadd_rn(hi, oh);
        float bp = __fsub_rn(s, hi);
        float e = __fadd_rn(__fsub_rn(hi, __fsub_rn(s, bp)), __fsub_rn(oh, bp));
        hi = s;
        lo = __fadd_rn(__fadd_rn(lo, ol), e);
    }
    float dotf = __fadd_rn(hi, lo);
    return __fsub_rn(__fadd_rn(g_S[n], g_e2[j]), 2.0f * dotf);
}

// ---------------------------------------------------------------------------
// K1: fused init + transpose/prep + e2 (independent block ranges)
// blocks [0,64): init; [64,576): prep; [576,1600): e2
// ---------------------------------------------------------------------------
__global__ void __launch_bounds__(256) front_kernel(const float* __restrict__ z,
                                                    const float* __restrict__ emb) {
    __shared__ float tile[32][CDIM + 1];
    int bid = blockIdx.x;
    int tid = threadIdx.x;
    if (bid < 64) {
        int i = bid * 256 + tid;
        if (i < NFEAT) g_exkey[i] = ~0ull;
        if (i < KCODE) { g_maxkey[i] = ~0ull; g_hist[i] = 0u; }
        if (i == 0) { g_sse = 0.0f; g_ent = 0.0f; g_util = 0u; g_xcnt = 0u; }
        return;
    }
    int tx = tid & 31, ty = tid >> 5;
    if (bid < 576) {
        int blk = bid - 64;
        int b = blk >> 5, h = blk & 31;
        const float* zp = z + (size_t)b * (CDIM * HDIM * WDIM) + h * WDIM;
#pragma unroll
        for (int i = 0; i < 32; i++) {
            int c = i * 8 + ty;
            tile[tx][c] = zp[c * (HDIM * WDIM) + tx];
        }
        __syncthreads();
        int nbase = b * 1024 + h * 32;
#pragma unroll
        for (int j = 0; j < 4; j++) {
            int w = ty * 4 + j;
            int n = nbase + w;
            float s = 0.0f;
#pragma unroll
            for (int i = 0; i < 8; i++) {
                int c = tx + 32 * i;
                float v = tile[w][c];
                g_zf[(size_t)n * CDIM + c] = v;
                g_zh[(size_t)n * CDIM + c] = __float2half_rn(v);
                s += v * v;
            }
#pragma unroll
            for (int m = 16; m; m >>= 1) s += __shfl_xor_sync(0xffffffffu, s, m);
            if (tx == 0) g_S[n] = s;
        }
        return;
    }
    {
        int j = (bid - 576) * 8 + ty;
        float s = 0.0f;
#pragma unroll
        for (int i = 0; i < 8; i++) {
            float v = emb[(size_t)j * CDIM + tx + 32 * i];
            g_eh[(size_t)j * CDIM + tx + 32 * i] = __float2half_rn(v * ESCALE);
            s += v * v;
        }
#pragma unroll
        for (int m = 16; m; m >>= 1) s += __shfl_xor_sync(0xffffffffu, s, m);
        if (tx == 0) g_e2[j] = s;
    }
}

// ---------------------------------------------------------------------------
// K3: fp16 m16n8k16 GEMM, 256 threads (8 warps 1Mx8N), 2 CTAs/SM.
// Fully unrolled k-block loop (static stage addressing); single barrier per
// k-block; pass-2 early-out; value-only column-max with bit-equality index
// recovery.
// ---------------------------------------------------------------------------
#define SM_ROWKEY 0             // 64 u64  [0,512)
#define SM_COLKEY 512           // 256 u64 [512,2560)
#define SM_SS     2560          // 64 f    [2560,2816)
#define SM_E2S    2816          // 256 f   [2816,3840)
#define SM_DATA   3840
#define STAGE_A   (BM * ROWB)               // 10240
#define STAGE_B   (BN * ROWB)               // 40960
#define STAGE_SZ  (STAGE_A + STAGE_B)       // 51200
#define GEMM_SMEM (SM_DATA + 2 * STAGE_SZ)  // 106240

__device__ __forceinline__ void cpa16(uint32_t dst, const void* src) {
    asm volatile("cp.async.cg.shared.global [%0], [%1], 16;"
                 :: "r"(dst), "l"(src));
}

#define MMA16(d, a0, a1, a2, a3, b0, b1)                                     \
    asm volatile(                                                            \
        "mma.sync.aligned.m16n8k16.row.col.f32.f16.f16.f32 "                 \
        "{%0,%1,%2,%3},{%4,%5,%6,%7},{%8,%9},{%0,%1,%2,%3};"                 \
        : "+f"(d[0]), "+f"(d[1]), "+f"(d[2]), "+f"(d[3])                     \
        : "r"(a0), "r"(a1), "r"(a2), "r"(a3), "r"(b0), "r"(b1))

extern __shared__ char dynsmem[];

__global__ void __launch_bounds__(256, 2)
gemm_mma_kernel(const float* __restrict__ emb) {
    const int tid  = threadIdx.x;
    const int lane = tid & 31;
    const int wn   = tid >> 5;      // warp 0..7 = N split
    const int gid  = lane >> 2;     // 0..7
    const int tig  = lane & 3;      // 0..3
    const int m0   = blockIdx.y * BM;
    const int j0   = blockIdx.x * BN;

    unsigned long long* rowkey = (unsigned long long*)(dynsmem + SM_ROWKEY);
    unsigned long long* colkey = (unsigned long long*)(dynsmem + SM_COLKEY);
    float* Ss  = (float*)(dynsmem + SM_SS);
    float* e2s = (float*)(dynsmem + SM_E2S);

    uint32_t smbase;
    asm("{ .reg .u64 t; cvta.to.shared.u64 t, %1; cvt.u32.u64 %0, t; }"
        : "=r"(smbase) : "l"(dynsmem));

    const int t8 = tid >> 3;            // 0..31
    const int c8 = tid & 7;             // 0..7
    const __half* gA0 = g_zh + (size_t)(m0 + t8) * CDIM + c8 * 8;
    const __half* gB0 = g_eh + (size_t)(j0 + t8) * CDIM + c8 * 8;
    const uint32_t dA0 = smbase + SM_DATA + t8 * ROWB + c8 * 16;
    const uint32_t dB0 = smbase + SM_DATA + STAGE_A + t8 * ROWB + c8 * 16;

    auto load_kb = [&](int s, int kb) {
        uint32_t so = s * STAGE_SZ;
        const __half* ga = gA0 + kb * BK;
        const __half* gb = gB0 + kb * BK;
#pragma unroll
        for (int i = 0; i < 2; i++)
            cpa16(dA0 + so + i * 32 * ROWB, ga + (size_t)i * 32 * CDIM);
#pragma unroll
        for (int i = 0; i < 8; i++)
            cpa16(dB0 + so + i * 32 * ROWB, gb + (size_t)i * 32 * CDIM);
    };

    if (tid < 64) { rowkey[tid] = ~0ull; Ss[tid] = g_S[m0 + tid]; }
    colkey[tid] = ~0ull;
    e2s[tid] = g_e2[j0 + tid];

    load_kb(0, 0);
    asm volatile("cp.async.commit_group;" ::: "memory");

    float acc[4][4][4];
#pragma unroll
    for (int nt = 0; nt < 4; nt++)
#pragma unroll
        for (int mt = 0; mt < 4; mt++)
#pragma unroll
            for (int c = 0; c < 4; c++) acc[nt][mt][c] = 0.0f;

    const int aBase2 = gid * (ROWB / 8) + tig;
    const int bBase2 = (wn * 32 + gid) * (ROWB / 8) + tig;

#pragma unroll
    for (int kb = 0; kb < NKB; kb++) {   // fully unrolled: static stages
        asm volatile("cp.async.wait_group 0;" ::: "memory");
        __syncthreads();   // single barrier per k-block

        const uint2* Af2 =
            (const uint2*)(dynsmem + SM_DATA + (kb & 1) * STAGE_SZ);
        const uint2* Bf2 = Af2 + STAGE_A / 8;

#pragma unroll
        for (int ks = 0; ks < BK / 16; ks++) {        // 4 k16-steps
            const int ko = ks * 4;
            uint2 alo[4], ahi[4], bv[4];
#pragma unroll
            for (int mt = 0; mt < 4; mt++) {
                int o = aBase2 + mt * 16 * (ROWB / 8) + ko;
                alo[mt] = Af2[o];
                ahi[mt] = Af2[o + 8 * (ROWB / 8)];
            }
#pragma unroll
            for (int nt = 0; nt < 4; nt++)
                bv[nt] = Bf2[bBase2 + nt * 8 * (ROWB / 8) + ko];
#pragma unroll
            for (int nt = 0; nt < 4; nt++)
#pragma unroll
                for (int mt = 0; mt < 4; mt++)
                    MMA16(acc[nt][mt], alo[mt].x, ahi[mt].x,
                          alo[mt].y, ahi[mt].y, bv[nt].x, bv[nt].y);
            if (ks == 0 && kb + 1 < NKB) {
                load_kb((kb + 1) & 1, kb + 1);
                asm volatile("cp.async.commit_group;" ::: "memory");
            }
        }
    }

    // ---- epilogue pass 1: d -> acc (in place), argmin/argmax ----
    float S_lo[4], S_hi[4];
#pragma unroll
    for (int mt = 0; mt < 4; mt++) {
        S_lo[mt] = Ss[mt * 16 + gid];
        S_hi[mt] = Ss[mt * 16 + gid + 8];
    }
    float bd_lo[4], bd_hi[4];
    int   bj_lo[4], bj_hi[4];
#pragma unroll
    for (int mt = 0; mt < 4; mt++) {
        bd_lo[mt] = __int_as_float(0x7f800000); bj_lo[mt] = 0;
        bd_hi[mt] = __int_as_float(0x7f800000); bj_hi[mt] = 0;
    }

#pragma unroll
    for (int nt = 0; nt < 4; nt++) {
        const int ca = wn * 32 + nt * 8 + 2 * tig;
        const float e2a = e2s[ca], e2b = e2s[ca + 1];
        const int ja = j0 + ca;
        float cva = __int_as_float(0xff800000), cvb = cva;   // -inf
#pragma unroll
        for (int mt = 0; mt < 4; mt++) {
            float d00 = fmaf(acc[nt][mt][0], DSCALE, S_lo[mt] + e2a);
            float d01 = fmaf(acc[nt][mt][1], DSCALE, S_lo[mt] + e2b);
            float d10 = fmaf(acc[nt][mt][2], DSCALE, S_hi[mt] + e2a);
            float d11 = fmaf(acc[nt][mt][3], DSCALE, S_hi[mt] + e2b);
            acc[nt][mt][0] = d00; acc[nt][mt][1] = d01;
            acc[nt][mt][2] = d10; acc[nt][mt][3] = d11;
            if (d00 < bd_lo[mt]) { bd_lo[mt] = d00; bj_lo[mt] = ja; }
            if (d01 < bd_lo[mt]) { bd_lo[mt] = d01; bj_lo[mt] = ja + 1; }
            if (d10 < bd_hi[mt]) { bd_hi[mt] = d10; bj_hi[mt] = ja; }
            if (d11 < bd_hi[mt]) { bd_hi[mt] = d11; bj_hi[mt] = ja + 1; }
            cva = fmaxf(cva, d00); cva = fmaxf(cva, d10);
            cvb = fmaxf(cvb, d01); cvb = fmaxf(cvb, d11);
        }
#pragma unroll
        for (int off = 4; off < 32; off <<= 1) {
            cva = fmaxf(cva, __shfl_xor_sync(0xffffffffu, cva, off));
            cvb = fmaxf(cvb, __shfl_xor_sync(0xffffffffu, cvb, off));
        }
        int ria = 0x7fffffff, rib = 0x7fffffff;
#pragma unroll
        for (int mt = 0; mt < 4; mt++) {
            const int rlo = m0 + mt * 16 + gid;
            if (acc[nt][mt][0] == cva) ria = min(ria, rlo);
            if (acc[nt][mt][2] == cva) ria = min(ria, rlo + 8);
            if (acc[nt][mt][1] == cvb) rib = min(rib, rlo);
            if (acc[nt][mt][3] == cvb) rib = min(rib, rlo + 8);
        }
#pragma unroll
        for (int off = 4; off < 32; off <<= 1) {
            ria = min(ria, __shfl_xor_sync(0xffffffffu, ria, off));
            rib = min(rib, __shfl_xor_sync(0xffffffffu, rib, off));
        }
        if (gid == 0) {
            atomicMin(&colkey[ca],
                      (((unsigned long long)(~ford(cva))) << 32) | (unsigned)ria);
            atomicMin(&colkey[ca + 1],
                      (((unsigned long long)(~ford(cvb))) << 32) | (unsigned)rib);
        }
    }
#pragma unroll
    for (int mt = 0; mt < 4; mt++) {
        unsigned long long klo =
            (((unsigned long long)ford(bd_lo[mt])) << 32) | (unsigned)bj_lo[mt];
        unsigned long long khi =
            (((unsigned long long)ford(bd_hi[mt])) << 32) | (unsigned)bj_hi[mt];
#pragma unroll
        for (int off = 1; off < 4; off <<= 1) {
            klo = min(klo, __shfl_xor_sync(0xffffffffu, klo, off));
            khi = min(khi, __shfl_xor_sync(0xffffffffu, khi, off));
        }
        if (tig == 0) {
            atomicMin(&rowkey[mt * 16 + gid], klo);
            atomicMin(&rowkey[mt * 16 + gid + 8], khi);
        }
    }
    __syncthreads();

    if (tid < 64) g_blockmin[m0 + tid][blockIdx.x] = rowkey[tid];
    atomicMin(&g_maxkey[j0 + tid], colkey[tid]);

    // ---- epilogue pass 2: append near-tie candidates (early-out) ----
#pragma unroll
    for (int mt = 0; mt < 4; mt++) {
        const int rl = mt * 16 + gid;
        const int rh = rl + 8;
        const unsigned long long rkl = rowkey[rl];
        const unsigned long long rkh = rowkey[rh];
        const float vl = unford((unsigned)(rkl >> 32)) + EPSB;
        const float vh = unford((unsigned)(rkh >> 32)) + EPSB;
        if (bd_lo[mt] < vl) {
#pragma unroll
            for (int nt = 0; nt < 4; nt++) {
                const int ca = wn * 32 + nt * 8 + 2 * tig;
                const unsigned ja = (unsigned)(j0 + ca);
                float d00 = acc[nt][mt][0];
                float d01 = acc[nt][mt][1];
                if (d00 < vl) {
                    unsigned long long k =
                        (((unsigned long long)ford(d00)) << 32) | ja;
                    if (k != rkl) {
                        unsigned slot = atomicAdd(&g_xcnt, 1u);
                        if (slot < MAXX)
                            g_extras[slot] = ((unsigned)(m0 + rl) << 13) | ja;
                    }
                }
                if (d01 < vl) {
                    unsigned long long k =
                        (((unsigned long long)ford(d01)) << 32) | (ja + 1);
                    if (k != rkl) {
                        unsigned slot = atomicAdd(&g_xcnt, 1u);
                        if (slot < MAXX)
                            g_extras[slot] = ((unsigned)(m0 + rl) << 13) | (ja + 1);
                    }
                }
            }
        }
        if (bd_hi[mt] < vh) {
#pragma unroll
            for (int nt = 0; nt < 4; nt++) {
                const int ca = wn * 32 + nt * 8 + 2 * tig;
                const unsigned ja = (unsigned)(j0 + ca);
                float d10 = acc[nt][mt][2];
                float d11 = acc[nt][mt][3];
                if (d10 < vh) {
                    unsigned long long k =
                        (((unsigned long long)ford(d10)) << 32) | ja;
                    if (k != rkh) {
                        unsigned slot = atomicAdd(&g_xcnt, 1u);
                        if (slot < MAXX)
                            g_extras[slot] = ((unsigned)(m0 + rh) << 13) | ja;
                    }
                }
                if (d11 < vh) {
                    unsigned long long k =
                        (((unsigned long long)ford(d11)) << 32) | (ja + 1);
                    if (k != rkh) {
                        unsigned slot = atomicAdd(&g_xcnt, 1u);
                        if (slot < MAXX)
                            g_extras[slot] = ((unsigned)(m0 + rh) << 13) | (ja + 1);
                    }
                }
            }
        }
    }
}

// ---------------------------------------------------------------------------
// K4a: exact recompute of appended extras
// ---------------------------------------------------------------------------
__global__ void __launch_bounds__(256) extras_kernel(const float* __restrict__ emb) {
    const unsigned cnt = min(g_xcnt, (unsigned)MAXX);
    const int lane = threadIdx.x & 31;
    const int wid = (blockIdx.x * blockDim.x + threadIdx.x) >> 5;
    const int nw = (gridDim.x * blockDim.x) >> 5;
    for (unsigned i = wid; i < cnt; i += nw) {
        unsigned e = g_extras[i];
        int n = e >> 13;
        int j = e & 8191;
        float d32 = exact_d32(emb, n, j, lane);
        unsigned long long key =
            (((unsigned long long)ford(d32)) << 32) | (unsigned)j;
        if (lane == 0) atomicMin(&g_exkey[n], key);
    }
}

// ---------------------------------------------------------------------------
// K4b: per-row token resolution (+ histogram); NJB==32 -> 1 key per lane
// ---------------------------------------------------------------------------
__global__ void __launch_bounds__(256) tokenfix_kernel(const float* __restrict__ emb) {
    const int lane = threadIdx.x & 31;
    const int wid = (blockIdx.x * blockDim.x + threadIdx.x) >> 5;
    const int nw = (gridDim.x * blockDim.x) >> 5;
    for (int n = wid; n < NFEAT; n += nw) {
        unsigned long long k = g_blockmin[n][lane];   // NJB == 32
        unsigned long long gm = k;
#pragma unroll
        for (int m = 16; m; m >>= 1)
            gm = min(gm, __shfl_xor_sync(0xffffffffu, gm, m));
        float thresh = unford((unsigned)(gm >> 32)) + EPSB;
        bool cand = unford((unsigned)(k >> 32)) < thresh;
        unsigned bal = __ballot_sync(0xffffffffu, cand);
        unsigned long long ex = g_exkey[n];
        unsigned tok;
        if (__popc(bal) == 1 && ex == ~0ull) {
            tok = (unsigned)(gm & 0xffffffffull);
        } else {
            unsigned long long best = ex;
            unsigned b = bal;
            while (b) {
                int src = __ffs(b) - 1;
                b &= b - 1;
                unsigned jj = __shfl_sync(0xffffffffu,
                                          (unsigned)(k & 0xffffffffull), src);
                float d32 = exact_d32(emb, n, (int)jj, lane);
                unsigned long long key =
                    (((unsigned long long)ford(d32)) << 32) | jj;
                best = min(best, key);
            }
            tok = (unsigned)(best & 0xffffffffull);
        }
        if (lane == 0) {
            g_token[n] = (int)tok;
            atomicAdd(&g_hist[tok], 1u);
        }
    }
}

// ---------------------------------------------------------------------------
// K5: fused z_q output + SSE (blocks [0,512)) and per-code update (rest)
// ---------------------------------------------------------------------------
__global__ void __launch_bounds__(256) back_kernel(const float* __restrict__ emb,
                                                   const float* __restrict__ eprob,
                                                   float* __restrict__ out) {
    __shared__ float rowbuf[32][CDIM + 1];
    __shared__ int stok[32];
    __shared__ float red[8];
    int bid = blockIdx.x;
    int tid = threadIdx.x;
    if (bid < 512) {
        int b = bid >> 5, h = bid & 31;
        int nbase = b * 1024 + h * 32;
        if (tid < 32) stok[tid] = g_token[nbase + tid];
        __syncthreads();
        float acc = 0.0f;
#pragma unroll 4
        for (int w = 0; w < 32; w++) {
            float v  = emb[(size_t)stok[w] * CDIM + tid];
            float zv = g_zf[(size_t)(nbase + w) * CDIM + tid];
            float diff = __fsub_rn(v, zv);
            acc = fmaf(diff, diff, acc);
            rowbuf[w][tid] = __fadd_rn(zv, diff);
        }
        float s = acc;
#pragma unroll
        for (int m = 16; m; m >>= 1) s += __shfl_xor_sync(0xffffffffu, s, m);
        if ((tid & 31) == 0) red[tid >> 5] = s;
        __syncthreads();
        if (tid == 0) {
            float t = 0.0f;
#pragma unroll
            for (int i = 0; i < 8; i++) t += red[i];
            atomicAdd(&g_sse, t);
        }
        int tx = tid & 31, ty = tid >> 5;
#pragma unroll
        for (int i = 0; i < 32; i++) {
            int c = i * 8 + ty;
            out[OUT_ZQ + (((size_t)b * CDIM + c) * HDIM + h) * WDIM + tx] =
                rowbuf[tx][c];
        }
        return;
    }
    {
        int j = bid - 512;
        int c = tid;
        unsigned hcnt = g_hist[j];
        float avg = (float)hcnt * (1.0f / 16384.0f);
        float np  = __fadd_rn(__fmul_rn(eprob[j], 0.99f), __fmul_rn(avg, 0.01f));
        float t = __fmul_rn(np, 8192.0f);
        t = __fmul_rn(t, 10.0f);
        t = __fdiv_rn(t, 0.01f);
        float decay = expf(-t - 0.001f);
        float omd = __fsub_rn(1.0f, decay);
        if (c == 0) {
            out[OUT_NPROB + j] = np;
            atomicAdd(&g_ent, avg * logf(avg + 1e-10f));
            if (hcnt > 0) atomicAdd(&g_util, 1u);
        }
        int fi = (int)(g_maxkey[j] & 0xffffffffull);
        float rf = g_zf[(size_t)fi * CDIM + c];
        float e  = emb[(size_t)j * CDIM + c];
        out[OUT_NEMB + (size_t)j * CDIM + c] =
            __fadd_rn(__fmul_rn(e, omd), __fmul_rn(rf, decay));
    }
}

// ---------------------------------------------------------------------------
__global__ void fin_kernel(float* __restrict__ out) {
    float sse = g_sse;
    float mse = sse / 4194304.0f;
    out[OUT_LOSS] = __fadd_rn(__fmul_rn(0.25f, mse), mse);
    out[OUT_QERR] = sse / 16384.0f;
    out[OUT_UTIL] = (float)g_util / 8192.0f;
    out[OUT_PERP] = expf(-g_ent);
}

// ---------------------------------------------------------------------------
extern "C" void kernel_launch(void* const* d_in, const int* in_sizes, int n_in,
                              void* d_out, int out_size) {
    (void)in_sizes; (void)n_in; (void)out_size;
    const float* z     = (const float*)d_in[0];
    const float* emb   = (const float*)d_in[1];
    const float* eprob = (const float*)d_in[2];
    float* out = (float*)d_out;

    static int smem_set = 0;
    if (!smem_set) {
        cudaFuncSetAttribute(gemm_mma_kernel,
                             cudaFuncAttributeMaxDynamicSharedMemorySize,
                             GEMM_SMEM);
        smem_set = 1;
    }

    front_kernel<<<1600, 256>>>(z, emb);
    gemm_mma_kernel<<<dim3(NJB, NFEAT / BM), 256, GEMM_SMEM>>>(emb);
    extras_kernel<<<1024, 256>>>(emb);
    tokenfix_kernel<<<2048, 256>>>(emb);
    back_kernel<<<512 + KCODE, 256>>>(emb, eprob, out);
    fin_kernel<<<1, 1>>>(out);
}